// round 1
// baseline (speedup 1.0000x reference)
#include <cuda_runtime.h>
#include <cstdint>
#include <math_constants.h>

#define FULLMASK 0xffffffffu

// ---------------- scratch (static device allocations; no cudaMalloc) --------
static __device__ float g_q[4096u * 4096u];   // 64 MB  xq (then roped)
static __device__ float g_k[4096u * 1024u];   // 16 MB  xk (then roped)
static __device__ float g_v[4096u * 1024u];   // 16 MB  xv
static __device__ float g_att[4096u * 4096u]; // 64 MB  attention output

// ---------------- helpers ---------------------------------------------------
__device__ __forceinline__ uint32_t f2tf32(float x) {
    uint32_t r;
    asm("cvt.rna.tf32.f32 %0, %1;" : "=r"(r) : "f"(x));
    return r;
}

__device__ __forceinline__ void mma_tf32(float* c, const uint32_t* a, const uint32_t* b) {
    asm volatile(
        "mma.sync.aligned.m16n8k8.row.col.f32.tf32.tf32.f32 "
        "{%0,%1,%2,%3}, {%4,%5,%6,%7}, {%8,%9}, {%0,%1,%2,%3};"
        : "+f"(c[0]), "+f"(c[1]), "+f"(c[2]), "+f"(c[3])
        : "r"(a[0]), "r"(a[1]), "r"(a[2]), "r"(a[3]), "r"(b[0]), "r"(b[1]));
}

__device__ __forceinline__ void cp_async16(void* smem, const void* gmem) {
    uint32_t s = (uint32_t)__cvta_generic_to_shared(smem);
    asm volatile("cp.async.cg.shared.global [%0], [%1], 16;" :: "r"(s), "l"(gmem));
}
__device__ __forceinline__ void cp_commit() {
    asm volatile("cp.async.commit_group;" ::: "memory");
}
template <int N>
__device__ __forceinline__ void cp_wait() {
    asm volatile("cp.async.wait_group %0;" :: "n"(N) : "memory");
}

// ---------------- TF32 GEMM: C[M,N] = A[M,K] * B[N,K]^T  (all fp32 row-major)
#define BM 128
#define BN 128
#define BKK 16
#define LDA (BKK + 4)   // 20 floats: conflict-free fragment loads

__global__ __launch_bounds__(256) void gemm_tf32(
    float* __restrict__ C, const float* __restrict__ A, const float* __restrict__ B,
    int M, int N, int K)
{
    __shared__ float As[2][BM][LDA];
    __shared__ float Bs[2][BN][LDA];

    const int bm = blockIdx.y * BM;
    const int bn = blockIdx.x * BN;
    const int tid = threadIdx.x;
    const int warp = tid >> 5, lane = tid & 31;
    const int wm = (warp & 3) << 5;   // 0,32,64,96
    const int wn = (warp >> 2) << 6;  // 0,64
    const int g = lane >> 2, t = lane & 3;

    float acc[2][8][4];
#pragma unroll
    for (int i = 0; i < 2; ++i)
#pragma unroll
        for (int j = 0; j < 8; ++j)
#pragma unroll
            for (int k = 0; k < 4; ++k) acc[i][j][k] = 0.f;

    auto load_stage = [&](int buf, int k0) {
#pragma unroll
        for (int c = 0; c < 2; ++c) {
            int id = tid + (c << 8);       // 0..511
            int row = id >> 2;             // 0..127
            int cg = (id & 3) << 2;        // float offset 0,4,8,12
            cp_async16(&As[buf][row][cg], A + (size_t)(bm + row) * K + k0 + cg);
            cp_async16(&Bs[buf][row][cg], B + (size_t)(bn + row) * K + k0 + cg);
        }
    };

    const int nIter = K / BKK;
    load_stage(0, 0);
    cp_commit();

    for (int it = 0; it < nIter; ++it) {
        const int buf = it & 1;
        if (it + 1 < nIter) {
            load_stage(buf ^ 1, (it + 1) * BKK);
            cp_commit();
            cp_wait<1>();
        } else {
            cp_wait<0>();
        }
        __syncthreads();

#pragma unroll
        for (int ks = 0; ks < 2; ++ks) {
            uint32_t af[2][4];
#pragma unroll
            for (int mt = 0; mt < 2; ++mt) {
                int r = wm + (mt << 4);
                af[mt][0] = f2tf32(As[buf][r + g][ks * 8 + t]);
                af[mt][1] = f2tf32(As[buf][r + g + 8][ks * 8 + t]);
                af[mt][2] = f2tf32(As[buf][r + g][ks * 8 + t + 4]);
                af[mt][3] = f2tf32(As[buf][r + g + 8][ks * 8 + t + 4]);
            }
#pragma unroll
            for (int nt = 0; nt < 8; ++nt) {
                uint32_t bf[2];
                int cN = wn + (nt << 3);
                bf[0] = f2tf32(Bs[buf][cN + g][ks * 8 + t]);
                bf[1] = f2tf32(Bs[buf][cN + g][ks * 8 + t + 4]);
                mma_tf32(acc[0][nt], af[0], bf);
                mma_tf32(acc[1][nt], af[1], bf);
            }
        }
        __syncthreads();
    }

    // epilogue
#pragma unroll
    for (int mt = 0; mt < 2; ++mt) {
        int r0 = bm + wm + (mt << 4) + g;
#pragma unroll
        for (int nt = 0; nt < 8; ++nt) {
            int cc = bn + wn + (nt << 3) + 2 * t;
            *(float2*)&C[(size_t)r0 * N + cc] = make_float2(acc[mt][nt][0], acc[mt][nt][1]);
            *(float2*)&C[(size_t)(r0 + 8) * N + cc] = make_float2(acc[mt][nt][2], acc[mt][nt][3]);
        }
    }
}

// ---------------- RoPE (interleaved pairs), in-place ------------------------
__global__ void rope_kernel(float* __restrict__ x, const float* __restrict__ cs,
                            const float* __restrict__ sn, int nheads)
{
    int idx = blockIdx.x * blockDim.x + threadIdx.x;
    int total = 4096 * nheads * 64;
    if (idx >= total) return;
    int i = idx & 63;                    // pair index 0..63
    int h = (idx >> 6) % nheads;
    int tok = idx / (64 * nheads);       // b*2048 + s
    int s = tok & 2047;
    float c = cs[s * 64 + i];
    float si = sn[s * 64 + i];
    float2* p = (float2*)(x + ((size_t)tok * nheads + h) * 128) + i;
    float2 v = *p;
    *p = make_float2(v.x * c - v.y * si, v.x * si + v.y * c);
}

// ---------------- causal GQA flash attention --------------------------------
#define QT 64
#define KT 32
#define LQS 132   // Q smem stride (conflict-free)
#define LKS 132   // K smem stride
#define LVS 136   // V smem stride (stride%32==8 -> conflict-free B-frag loads)

__global__ __launch_bounds__(128) void attn_kernel(
    float* __restrict__ O, const float* __restrict__ Q,
    const float* __restrict__ Kg, const float* __restrict__ Vg)
{
    __shared__ float sbuf[KT * LKS + KT * LVS];   // 8576 floats; Q staging uses 64*132=8448
    float* Ks = sbuf;
    float* Vs = sbuf + KT * LKS;

    const int qtile = blockIdx.x;  // 0..31
    const int h = blockIdx.y;      // 0..31
    const int b = blockIdx.z;      // 0..1
    const int kvh = h >> 2;        // N_REP = 4
    const int tid = threadIdx.x;
    const int warp = tid >> 5, lane = tid & 31;
    const int g = lane >> 2, t = lane & 3;
    const int q0 = qtile * QT;

    // fold 1/sqrt(128) * log2(e) into Q so softmax uses exp2
    const float qscale = 0.08838834764831845f * 1.4426950408889634f;

    // stage Q tile into smem (scaled), coalesced
    {
        float* Qs = sbuf;
#pragma unroll
        for (int pass = 0; pass < 16; ++pass) {
            int r = pass * 4 + (tid >> 5);
            int c = (tid & 31) << 2;
            float4 v = *(const float4*)&Q[(size_t)(b * 2048 + q0 + r) * 4096 + h * 128 + c];
            Qs[r * LQS + c + 0] = v.x * qscale;
            Qs[r * LQS + c + 1] = v.y * qscale;
            Qs[r * LQS + c + 2] = v.z * qscale;
            Qs[r * LQS + c + 3] = v.w * qscale;
        }
    }
    __syncthreads();

    // per-warp Q fragments (16 k-steps over HD=128)
    uint32_t qf[16][4];
    {
        const float* Qs = sbuf;
        int r = warp * 16;
#pragma unroll
        for (int kc = 0; kc < 16; ++kc) {
            qf[kc][0] = f2tf32(Qs[(r + g) * LQS + kc * 8 + t]);
            qf[kc][1] = f2tf32(Qs[(r + g + 8) * LQS + kc * 8 + t]);
            qf[kc][2] = f2tf32(Qs[(r + g) * LQS + kc * 8 + t + 4]);
            qf[kc][3] = f2tf32(Qs[(r + g + 8) * LQS + kc * 8 + t + 4]);
        }
    }
    __syncthreads();

    float o[16][4];
#pragma unroll
    for (int i = 0; i < 16; ++i)
#pragma unroll
        for (int j = 0; j < 4; ++j) o[i][j] = 0.f;

    float m0 = -CUDART_INF_F, m1 = -CUDART_INF_F, l0 = 0.f, l1 = 0.f;
    const int rowg0 = q0 + warp * 16 + g;
    const int rowg1 = rowg0 + 8;

    const int src1 = (lane & 28) | (t >> 1);
    const int src2 = src1 | 2;
    const bool odd = (t & 1);

    for (int kv0 = 0; kv0 < q0 + QT; kv0 += KT) {
        // load K,V tiles, coalesced
#pragma unroll
        for (int pass = 0; pass < 8; ++pass) {
            int r = pass * 4 + (tid >> 5);
            int c = (tid & 31) << 2;
            size_t gidx = (size_t)(b * 2048 + kv0 + r) * 1024 + kvh * 128 + c;
            *(float4*)&Ks[r * LKS + c] = *(const float4*)&Kg[gidx];
            *(float4*)&Vs[r * LVS + c] = *(const float4*)&Vg[gidx];
        }
        __syncthreads();

        // S = Q * K^T  (m16 x n32 per warp)
        float sv[4][4];
#pragma unroll
        for (int nt = 0; nt < 4; ++nt)
#pragma unroll
            for (int j = 0; j < 4; ++j) sv[nt][j] = 0.f;

#pragma unroll
        for (int kc = 0; kc < 16; ++kc) {
#pragma unroll
            for (int nt = 0; nt < 4; ++nt) {
                uint32_t bf[2];
                bf[0] = f2tf32(Ks[(nt * 8 + g) * LKS + kc * 8 + t]);
                bf[1] = f2tf32(Ks[(nt * 8 + g) * LKS + kc * 8 + t + 4]);
                mma_tf32(sv[nt], qf[kc], bf);
            }
        }

        // causal mask (only tiles crossing the diagonal)
        if (kv0 + KT > q0) {
#pragma unroll
            for (int nt = 0; nt < 4; ++nt) {
                int c0 = kv0 + nt * 8 + 2 * t;
                if (c0 > rowg0) sv[nt][0] = -CUDART_INF_F;
                if (c0 + 1 > rowg0) sv[nt][1] = -CUDART_INF_F;
                if (c0 > rowg1) sv[nt][2] = -CUDART_INF_F;
                if (c0 + 1 > rowg1) sv[nt][3] = -CUDART_INF_F;
            }
        }

        // online softmax (rows owned entirely within the warp)
        float mx0 = -CUDART_INF_F, mx1 = -CUDART_INF_F;
#pragma unroll
        for (int nt = 0; nt < 4; ++nt) {
            mx0 = fmaxf(mx0, fmaxf(sv[nt][0], sv[nt][1]));
            mx1 = fmaxf(mx1, fmaxf(sv[nt][2], sv[nt][3]));
        }
        mx0 = fmaxf(mx0, __shfl_xor_sync(FULLMASK, mx0, 1));
        mx0 = fmaxf(mx0, __shfl_xor_sync(FULLMASK, mx0, 2));
        mx1 = fmaxf(mx1, __shfl_xor_sync(FULLMASK, mx1, 1));
        mx1 = fmaxf(mx1, __shfl_xor_sync(FULLMASK, mx1, 2));

        float nm0 = fmaxf(m0, mx0), nm1 = fmaxf(m1, mx1);
        float a0 = exp2f(m0 - nm0), a1 = exp2f(m1 - nm1);
        m0 = nm0; m1 = nm1;

        float rs0 = 0.f, rs1 = 0.f;
#pragma unroll
        for (int nt = 0; nt < 4; ++nt) {
            sv[nt][0] = exp2f(sv[nt][0] - m0);
            sv[nt][1] = exp2f(sv[nt][1] - m0);
            sv[nt][2] = exp2f(sv[nt][2] - m1);
            sv[nt][3] = exp2f(sv[nt][3] - m1);
            rs0 += sv[nt][0] + sv[nt][1];
            rs1 += sv[nt][2] + sv[nt][3];
        }
        rs0 += __shfl_xor_sync(FULLMASK, rs0, 1);
        rs0 += __shfl_xor_sync(FULLMASK, rs0, 2);
        rs1 += __shfl_xor_sync(FULLMASK, rs1, 1);
        rs1 += __shfl_xor_sync(FULLMASK, rs1, 2);
        l0 = l0 * a0 + rs0;
        l1 = l1 * a1 + rs1;

#pragma unroll
        for (int ht = 0; ht < 16; ++ht) {
            o[ht][0] *= a0; o[ht][1] *= a0;
            o[ht][2] *= a1; o[ht][3] *= a1;
        }

        // O += P * V : relayout P (C-frag) -> A-frag via quad shuffles
#pragma unroll
        for (int kc = 0; kc < 4; ++kc) {
            float x0 = __shfl_sync(FULLMASK, sv[kc][0], src1);
            float x1 = __shfl_sync(FULLMASK, sv[kc][1], src1);
            float x2 = __shfl_sync(FULLMASK, sv[kc][2], src1);
            float x3 = __shfl_sync(FULLMASK, sv[kc][3], src1);
            float y0 = __shfl_sync(FULLMASK, sv[kc][0], src2);
            float y1 = __shfl_sync(FULLMASK, sv[kc][1], src2);
            float y2 = __shfl_sync(FULLMASK, sv[kc][2], src2);
            float y3 = __shfl_sync(FULLMASK, sv[kc][3], src2);
            uint32_t af[4];
            af[0] = f2tf32(odd ? x1 : x0);
            af[1] = f2tf32(odd ? x3 : x2);
            af[2] = f2tf32(odd ? y1 : y0);
            af[3] = f2tf32(odd ? y3 : y2);
#pragma unroll
            for (int ht = 0; ht < 16; ++ht) {
                uint32_t bf[2];
                bf[0] = f2tf32(Vs[(kc * 8 + t) * LVS + ht * 8 + g]);
                bf[1] = f2tf32(Vs[(kc * 8 + t + 4) * LVS + ht * 8 + g]);
                mma_tf32(o[ht], af, bf);
            }
        }
        __syncthreads();
    }

    // epilogue: normalize and store [token, h*128 + hd]
    float i0 = 1.f / l0, i1 = 1.f / l1;
#pragma unroll
    for (int ht = 0; ht < 16; ++ht) {
        size_t base = (size_t)(b * 2048 + rowg0) * 4096 + h * 128 + ht * 8 + 2 * t;
        *(float2*)&O[base] = make_float2(o[ht][0] * i0, o[ht][1] * i0);
        *(float2*)&O[base + (size_t)8 * 4096] = make_float2(o[ht][2] * i1, o[ht][3] * i1);
    }
}

// ---------------- entry -----------------------------------------------------
extern "C" void kernel_launch(void* const* d_in, const int* in_sizes, int n_in,
                              void* d_out, int out_size)
{
    const float* x  = (const float*)d_in[0];
    const float* wq = (const float*)d_in[1];
    const float* wk = (const float*)d_in[2];
    const float* wv = (const float*)d_in[3];
    const float* wo = (const float*)d_in[4];
    const float* fc = (const float*)d_in[5];
    const float* fs = (const float*)d_in[6];
    // d_in[7] mask (causal, reimplemented), d_in[8..9] caches, d_in[10] start_pos==0: unused
    float* out = (float*)d_out;

    float *gq, *gk, *gv, *ga;
    cudaGetSymbolAddress((void**)&gq, g_q);
    cudaGetSymbolAddress((void**)&gk, g_k);
    cudaGetSymbolAddress((void**)&gv, g_v);
    cudaGetSymbolAddress((void**)&ga, g_att);

    // QKV projections
    gemm_tf32<<<dim3(4096 / BN, 4096 / BM), 256>>>(gq, x, wq, 4096, 4096, 4096);
    gemm_tf32<<<dim3(1024 / BN, 4096 / BM), 256>>>(gk, x, wk, 4096, 1024, 4096);
    gemm_tf32<<<dim3(1024 / BN, 4096 / BM), 256>>>(gv, x, wv, 4096, 1024, 4096);

    // RoPE on Q and K
    rope_kernel<<<(4096 * 32 * 64 + 255) / 256, 256>>>(gq, fc, fs, 32);
    rope_kernel<<<(4096 * 8 * 64 + 255) / 256, 256>>>(gk, fc, fs, 8);

    // attention
    attn_kernel<<<dim3(32, 32, 2), 128>>>(ga, gq, gk, gv);

    // output projection -> d_out
    gemm_tf32<<<dim3(4096 / BN, 4096 / BM), 256>>>(out, ga, wo, 4096, 4096, 4096);
}

// round 3
// speedup vs baseline: 1.1590x; 1.1590x over previous
#include <cuda_runtime.h>
#include <cstdint>
#include <math_constants.h>

#define FULLMASK 0xffffffffu

// ---------------- scratch (static device arrays; no cudaMalloc) -------------
static __device__ float g_xr[4096u * 4096u];   // x rounded to tf32
static __device__ float g_wqr[4096u * 4096u];
static __device__ float g_wkr[1024u * 4096u];
static __device__ float g_wvr[1024u * 4096u];
static __device__ float g_wor[4096u * 4096u];
static __device__ float g_q[4096u * 4096u];    // xq (roped+rounded)
static __device__ float g_k[4096u * 1024u];    // xk (roped+rounded)
static __device__ float g_v[4096u * 1024u];    // xv (rounded)
static __device__ float g_att[4096u * 4096u];  // attention out (rounded)

// ---------------- helpers ---------------------------------------------------
__device__ __forceinline__ uint32_t f2tf32(float x) {
    uint32_t r;
    asm("cvt.rna.tf32.f32 %0, %1;" : "=r"(r) : "f"(x));
    return r;
}

// operands are pre-rounded tf32 bit patterns; hardware truncation is exact
__device__ __forceinline__ void mma_tf32(float* c, const uint32_t* a, const uint32_t* b) {
    asm volatile(
        "mma.sync.aligned.m16n8k8.row.col.f32.tf32.tf32.f32 "
        "{%0,%1,%2,%3}, {%4,%5,%6,%7}, {%8,%9}, {%0,%1,%2,%3};"
        : "+f"(c[0]), "+f"(c[1]), "+f"(c[2]), "+f"(c[3])
        : "r"(a[0]), "r"(a[1]), "r"(a[2]), "r"(a[3]), "r"(b[0]), "r"(b[1]));
}

__device__ __forceinline__ void cp_async16(void* smem, const void* gmem) {
    uint32_t s = (uint32_t)__cvta_generic_to_shared(smem);
    asm volatile("cp.async.cg.shared.global [%0], [%1], 16;" :: "r"(s), "l"(gmem));
}
__device__ __forceinline__ void cp_commit() {
    asm volatile("cp.async.commit_group;" ::: "memory");
}
template <int N>
__device__ __forceinline__ void cp_wait() {
    asm volatile("cp.async.wait_group %0;" :: "n"(N) : "memory");
}

// ---------------- pre-round fp32 -> tf32 bit pattern ------------------------
__global__ void round_tf32_kernel(float* __restrict__ dst, const float* __restrict__ src, int n4) {
    int i = blockIdx.x * blockDim.x + threadIdx.x;
    if (i >= n4) return;
    float4 v = ((const float4*)src)[i];
    v.x = __uint_as_float(f2tf32(v.x));
    v.y = __uint_as_float(f2tf32(v.y));
    v.z = __uint_as_float(f2tf32(v.z));
    v.w = __uint_as_float(f2tf32(v.w));
    ((float4*)dst)[i] = v;
}

// ---------------- TF32 GEMM: C[M,N] = A[M,K] * B[N,K]^T  --------------------
// Inputs pre-rounded to tf32. k-slot permutation {2t,2t+1} -> all fragment
// loads are LDS.64; stride 24 floats (== 24 mod 32) -> conflict-free.
#define BM 128
#define BN 128
#define BKK 16
#define LDA 24

__global__ __launch_bounds__(256, 2) void gemm_tf32(
    float* __restrict__ C, const float* __restrict__ A, const float* __restrict__ B,
    int N, int K)
{
    __shared__ float As[2][BM][LDA];
    __shared__ float Bs[2][BN][LDA];

    const int bm = blockIdx.y * BM;
    const int bn = blockIdx.x * BN;
    const int tid = threadIdx.x;
    const int warp = tid >> 5, lane = tid & 31;
    const int wm = (warp & 3) << 5;   // 0,32,64,96
    const int wn = (warp >> 2) << 6;  // 0,64
    const int g = lane >> 2, t = lane & 3;

    float acc[2][8][4];
#pragma unroll
    for (int i = 0; i < 2; ++i)
#pragma unroll
        for (int j = 0; j < 8; ++j)
#pragma unroll
            for (int k = 0; k < 4; ++k) acc[i][j][k] = 0.f;

    auto load_stage = [&](int buf, int k0) {
#pragma unroll
        for (int c = 0; c < 2; ++c) {
            int id = tid + (c << 8);       // 0..511
            int row = id >> 2;             // 0..127
            int cg = (id & 3) << 2;        // 0,4,8,12
            cp_async16(&As[buf][row][cg], A + (size_t)(bm + row) * K + k0 + cg);
            cp_async16(&Bs[buf][row][cg], B + (size_t)(bn + row) * K + k0 + cg);
        }
    };

    const int nIter = K / BKK;
    load_stage(0, 0);
    cp_commit();

    for (int it = 0; it < nIter; ++it) {
        const int buf = it & 1;
        if (it + 1 < nIter) {
            load_stage(buf ^ 1, (it + 1) * BKK);
            cp_commit();
            cp_wait<1>();
        } else {
            cp_wait<0>();
        }
        __syncthreads();

#pragma unroll
        for (int ks = 0; ks < 2; ++ks) {
            const int kcol = ks * 8 + 2 * t;
            uint32_t af[2][4];
#pragma unroll
            for (int mt = 0; mt < 2; ++mt) {
                int r = wm + (mt << 4);
                float2 p0 = *(const float2*)&As[buf][r + g][kcol];
                float2 p1 = *(const float2*)&As[buf][r + g + 8][kcol];
                af[mt][0] = __float_as_uint(p0.x);
                af[mt][1] = __float_as_uint(p1.x);
                af[mt][2] = __float_as_uint(p0.y);
                af[mt][3] = __float_as_uint(p1.y);
            }
#pragma unroll
            for (int nt = 0; nt < 8; ++nt) {
                float2 bb = *(const float2*)&Bs[buf][wn + (nt << 3) + g][kcol];
                uint32_t bf[2] = {__float_as_uint(bb.x), __float_as_uint(bb.y)};
                mma_tf32(acc[0][nt], af[0], bf);
                mma_tf32(acc[1][nt], af[1], bf);
            }
        }
        __syncthreads();
    }

#pragma unroll
    for (int mt = 0; mt < 2; ++mt) {
        int r0 = bm + wm + (mt << 4) + g;
#pragma unroll
        for (int nt = 0; nt < 8; ++nt) {
            int cc = bn + wn + (nt << 3) + 2 * t;
            *(float2*)&C[(size_t)r0 * N + cc] = make_float2(acc[mt][nt][0], acc[mt][nt][1]);
            *(float2*)&C[(size_t)(r0 + 8) * N + cc] = make_float2(acc[mt][nt][2], acc[mt][nt][3]);
        }
    }
}

// ---------------- RoPE (interleaved pairs), in-place, rounds to tf32 --------
__global__ void rope_kernel(float* __restrict__ x, const float* __restrict__ cs,
                            const float* __restrict__ sn, int nheads)
{
    int idx = blockIdx.x * blockDim.x + threadIdx.x;
    int total = 4096 * nheads * 64;
    if (idx >= total) return;
    int i = idx & 63;
    int h = (idx >> 6) % nheads;
    int tok = idx / (64 * nheads);
    int s = tok & 2047;
    float c = cs[s * 64 + i];
    float si = sn[s * 64 + i];
    float2* p = (float2*)(x + ((size_t)tok * nheads + h) * 128) + i;
    float2 v = *p;
    *p = make_float2(__uint_as_float(f2tf32(v.x * c - v.y * si)),
                     __uint_as_float(f2tf32(v.x * si + v.y * c)));
}

// ---------------- causal GQA flash attention --------------------------------
#define QT 64
#define KT 32
#define LQS 152   // ==24 mod 32: conflict-free float2 frag loads, >=128 cols
#define LKS 152
#define LVS 136   // ==8 mod 32: conflict-free V B-frag loads

__global__ __launch_bounds__(128) void attn_kernel(
    float* __restrict__ O, const float* __restrict__ Q,
    const float* __restrict__ Kg, const float* __restrict__ Vg)
{
    __shared__ float sbuf[QT * LQS];   // 9728 floats; K+V reuse: 32*152+32*136=9216
    float* Ks = sbuf;
    float* Vs = sbuf + KT * LKS;

    const int qtile = blockIdx.x;
    const int h = blockIdx.y;
    const int b = blockIdx.z;
    const int kvh = h >> 2;
    const int tid = threadIdx.x;
    const int warp = tid >> 5, lane = tid & 31;
    const int g = lane >> 2, t = lane & 3;
    const int q0 = qtile * QT;

    const float qscale = 0.08838834764831845f * 1.4426950408889634f;

    // stage Q tile (scaled + re-rounded to tf32)
    {
        float* Qs = sbuf;
#pragma unroll
        for (int pass = 0; pass < 16; ++pass) {
            int r = pass * 4 + (tid >> 5);
            int c = (tid & 31) << 2;
            float4 v = *(const float4*)&Q[(size_t)(b * 2048 + q0 + r) * 4096 + h * 128 + c];
            Qs[r * LQS + c + 0] = __uint_as_float(f2tf32(v.x * qscale));
            Qs[r * LQS + c + 1] = __uint_as_float(f2tf32(v.y * qscale));
            Qs[r * LQS + c + 2] = __uint_as_float(f2tf32(v.z * qscale));
            Qs[r * LQS + c + 3] = __uint_as_float(f2tf32(v.w * qscale));
        }
    }
    __syncthreads();

    // per-warp Q fragments, k-slots {2t,2t+1}
    uint32_t qf[16][4];
    {
        const float* Qs = sbuf;
        int r = warp * 16;
#pragma unroll
        for (int kc = 0; kc < 16; ++kc) {
            float2 p0 = *(const float2*)&Qs[(r + g) * LQS + kc * 8 + 2 * t];
            float2 p1 = *(const float2*)&Qs[(r + g + 8) * LQS + kc * 8 + 2 * t];
            qf[kc][0] = __float_as_uint(p0.x);
            qf[kc][1] = __float_as_uint(p1.x);
            qf[kc][2] = __float_as_uint(p0.y);
            qf[kc][3] = __float_as_uint(p1.y);
        }
    }
    __syncthreads();

    float o[16][4];
#pragma unroll
    for (int i = 0; i < 16; ++i)
#pragma unroll
        for (int j = 0; j < 4; ++j) o[i][j] = 0.f;

    float m0 = -CUDART_INF_F, m1 = -CUDART_INF_F, l0 = 0.f, l1 = 0.f;
    const int rowg0 = q0 + warp * 16 + g;
    const int rowg1 = rowg0 + 8;

    const int src1 = (lane & 28) | (t >> 1);
    const int src2 = src1 | 2;
    const bool odd = (t & 1);

    for (int kv0 = 0; kv0 < q0 + QT; kv0 += KT) {
#pragma unroll
        for (int pass = 0; pass < 8; ++pass) {
            int r = pass * 4 + (tid >> 5);
            int c = (tid & 31) << 2;
            size_t gidx = (size_t)(b * 2048 + kv0 + r) * 1024 + kvh * 128 + c;
            *(float4*)&Ks[r * LKS + c] = *(const float4*)&Kg[gidx];
            *(float4*)&Vs[r * LVS + c] = *(const float4*)&Vg[gidx];
        }
        __syncthreads();

        // S = Q * K^T
        float sv[4][4];
#pragma unroll
        for (int nt = 0; nt < 4; ++nt)
#pragma unroll
            for (int j = 0; j < 4; ++j) sv[nt][j] = 0.f;

#pragma unroll
        for (int kc = 0; kc < 16; ++kc) {
            const int kcol = kc * 8 + 2 * t;
#pragma unroll
            for (int nt = 0; nt < 4; ++nt) {
                float2 kb = *(const float2*)&Ks[(nt * 8 + g) * LKS + kcol];
                uint32_t bf[2] = {__float_as_uint(kb.x), __float_as_uint(kb.y)};
                mma_tf32(sv[nt], qf[kc], bf);
            }
        }

        if (kv0 + KT > q0) {
#pragma unroll
            for (int nt = 0; nt < 4; ++nt) {
                int c0 = kv0 + nt * 8 + 2 * t;
                if (c0 > rowg0) sv[nt][0] = -CUDART_INF_F;
                if (c0 + 1 > rowg0) sv[nt][1] = -CUDART_INF_F;
                if (c0 > rowg1) sv[nt][2] = -CUDART_INF_F;
                if (c0 + 1 > rowg1) sv[nt][3] = -CUDART_INF_F;
            }
        }

        float mx0 = -CUDART_INF_F, mx1 = -CUDART_INF_F;
#pragma unroll
        for (int nt = 0; nt < 4; ++nt) {
            mx0 = fmaxf(mx0, fmaxf(sv[nt][0], sv[nt][1]));
            mx1 = fmaxf(mx1, fmaxf(sv[nt][2], sv[nt][3]));
        }
        mx0 = fmaxf(mx0, __shfl_xor_sync(FULLMASK, mx0, 1));
        mx0 = fmaxf(mx0, __shfl_xor_sync(FULLMASK, mx0, 2));
        mx1 = fmaxf(mx1, __shfl_xor_sync(FULLMASK, mx1, 1));
        mx1 = fmaxf(mx1, __shfl_xor_sync(FULLMASK, mx1, 2));

        float nm0 = fmaxf(m0, mx0), nm1 = fmaxf(m1, mx1);
        float a0 = exp2f(m0 - nm0), a1 = exp2f(m1 - nm1);
        m0 = nm0; m1 = nm1;

        float rs0 = 0.f, rs1 = 0.f;
#pragma unroll
        for (int nt = 0; nt < 4; ++nt) {
            sv[nt][0] = exp2f(sv[nt][0] - m0);
            sv[nt][1] = exp2f(sv[nt][1] - m0);
            sv[nt][2] = exp2f(sv[nt][2] - m1);
            sv[nt][3] = exp2f(sv[nt][3] - m1);
            rs0 += sv[nt][0] + sv[nt][1];
            rs1 += sv[nt][2] + sv[nt][3];
        }
        rs0 += __shfl_xor_sync(FULLMASK, rs0, 1);
        rs0 += __shfl_xor_sync(FULLMASK, rs0, 2);
        rs1 += __shfl_xor_sync(FULLMASK, rs1, 1);
        rs1 += __shfl_xor_sync(FULLMASK, rs1, 2);
        l0 = l0 * a0 + rs0;
        l1 = l1 * a1 + rs1;

#pragma unroll
        for (int ht = 0; ht < 16; ++ht) {
            o[ht][0] *= a0; o[ht][1] *= a0;
            o[ht][2] *= a1; o[ht][3] *= a1;
        }

        // O += P * V (standard k-slots {t,t+4}; V pre-rounded, no cvt)
#pragma unroll
        for (int kc = 0; kc < 4; ++kc) {
            float x0 = __shfl_sync(FULLMASK, sv[kc][0], src1);
            float x1 = __shfl_sync(FULLMASK, sv[kc][1], src1);
            float x2 = __shfl_sync(FULLMASK, sv[kc][2], src1);
            float x3 = __shfl_sync(FULLMASK, sv[kc][3], src1);
            float y0 = __shfl_sync(FULLMASK, sv[kc][0], src2);
            float y1 = __shfl_sync(FULLMASK, sv[kc][1], src2);
            float y2 = __shfl_sync(FULLMASK, sv[kc][2], src2);
            float y3 = __shfl_sync(FULLMASK, sv[kc][3], src2);
            uint32_t af[4];
            af[0] = f2tf32(odd ? x1 : x0);
            af[1] = f2tf32(odd ? x3 : x2);
            af[2] = f2tf32(odd ? y1 : y0);
            af[3] = f2tf32(odd ? y3 : y2);
#pragma unroll
            for (int ht = 0; ht < 16; ++ht) {
                uint32_t bf[2];
                bf[0] = __float_as_uint(Vs[(kc * 8 + t) * LVS + ht * 8 + g]);
                bf[1] = __float_as_uint(Vs[(kc * 8 + t + 4) * LVS + ht * 8 + g]);
                mma_tf32(o[ht], af, bf);
            }
        }
        __syncthreads();
    }

    // epilogue: normalize, round to tf32 (feeds O-proj GEMM), store
    float i0 = 1.f / l0, i1 = 1.f / l1;
#pragma unroll
    for (int ht = 0; ht < 16; ++ht) {
        size_t base = (size_t)(b * 2048 + rowg0) * 4096 + h * 128 + ht * 8 + 2 * t;
        *(float2*)&O[base] = make_float2(__uint_as_float(f2tf32(o[ht][0] * i0)),
                                         __uint_as_float(f2tf32(o[ht][1] * i0)));
        *(float2*)&O[base + (size_t)8 * 4096] =
            make_float2(__uint_as_float(f2tf32(o[ht][2] * i1)),
                        __uint_as_float(f2tf32(o[ht][3] * i1)));
    }
}

// ---------------- entry -----------------------------------------------------
extern "C" void kernel_launch(void* const* d_in, const int* in_sizes, int n_in,
                              void* d_out, int out_size)
{
    const float* x  = (const float*)d_in[0];
    const float* wq = (const float*)d_in[1];
    const float* wk = (const float*)d_in[2];
    const float* wv = (const float*)d_in[3];
    const float* wo = (const float*)d_in[4];
    const float* fc = (const float*)d_in[5];
    const float* fs = (const float*)d_in[6];
    float* out = (float*)d_out;

    float *gxr, *gwqr, *gwkr, *gwvr, *gwor, *gq, *gk, *gv, *ga;
    cudaGetSymbolAddress((void**)&gxr,  g_xr);
    cudaGetSymbolAddress((void**)&gwqr, g_wqr);
    cudaGetSymbolAddress((void**)&gwkr, g_wkr);
    cudaGetSymbolAddress((void**)&gwvr, g_wvr);
    cudaGetSymbolAddress((void**)&gwor, g_wor);
    cudaGetSymbolAddress((void**)&gq, g_q);
    cudaGetSymbolAddress((void**)&gk, g_k);
    cudaGetSymbolAddress((void**)&gv, g_v);
    cudaGetSymbolAddress((void**)&ga, g_att);

    // pre-round all GEMM inputs to tf32
    round_tf32_kernel<<<16384, 256>>>(gxr,  x,  4194304);
    round_tf32_kernel<<<16384, 256>>>(gwqr, wq, 4194304);
    round_tf32_kernel<<<4096,  256>>>(gwkr, wk, 1048576);
    round_tf32_kernel<<<4096,  256>>>(gwvr, wv, 1048576);
    round_tf32_kernel<<<16384, 256>>>(gwor, wo, 4194304);

    // QKV projections
    gemm_tf32<<<dim3(32, 32), 256>>>(gq, gxr, gwqr, 4096, 4096);
    gemm_tf32<<<dim3(8, 32),  256>>>(gk, gxr, gwkr, 1024, 4096);
    gemm_tf32<<<dim3(8, 32),  256>>>(gv, gxr, gwvr, 1024, 4096);

    // RoPE on Q,K (rounds to tf32); round V in place (idempotent)
    rope_kernel<<<(4096 * 32 * 64 + 255) / 256, 256>>>(gq, fc, fs, 32);
    rope_kernel<<<(4096 * 8 * 64 + 255) / 256, 256>>>(gk, fc, fs, 8);
    round_tf32_kernel<<<4096, 256>>>(gv, gv, 1048576);

    // attention
    attn_kernel<<<dim3(32, 32, 2), 128>>>(ga, gq, gk, gv);

    // output projection -> d_out
    gemm_tf32<<<dim3(32, 32), 256>>>(out, ga, gwor, 4096, 4096);
}

// round 4
// speedup vs baseline: 1.2135x; 1.0470x over previous
#include <cuda_runtime.h>
#include <cstdint>
#include <math_constants.h>

#define FULLMASK 0xffffffffu

// ---------------- scratch (static device arrays; no cudaMalloc) -------------
static __device__ float g_xr[4096u * 4096u];   // x rounded to tf32
static __device__ float g_wqr[4096u * 4096u];
static __device__ float g_wkr[1024u * 4096u];
static __device__ float g_wvr[1024u * 4096u];
static __device__ float g_wor[4096u * 4096u];
static __device__ float g_q[4096u * 4096u];    // xq (roped+rounded)
static __device__ float g_k[4096u * 1024u];    // xk (roped+rounded)
static __device__ float g_v[4096u * 1024u];    // xv (rounded by gemm epilogue)
static __device__ float g_att[4096u * 4096u];  // attention out (rounded)

// ---------------- helpers ---------------------------------------------------
__device__ __forceinline__ uint32_t f2tf32(float x) {
    uint32_t r;
    asm("cvt.rna.tf32.f32 %0, %1;" : "=r"(r) : "f"(x));
    return r;
}
__device__ __forceinline__ uint32_t fu(float x) { return __float_as_uint(x); }

// operands are pre-rounded tf32 bit patterns; hardware truncation is exact
__device__ __forceinline__ void mma_tf32(float* c, const uint32_t* a, const uint32_t* b) {
    asm volatile(
        "mma.sync.aligned.m16n8k8.row.col.f32.tf32.tf32.f32 "
        "{%0,%1,%2,%3}, {%4,%5,%6,%7}, {%8,%9}, {%0,%1,%2,%3};"
        : "+f"(c[0]), "+f"(c[1]), "+f"(c[2]), "+f"(c[3])
        : "r"(a[0]), "r"(a[1]), "r"(a[2]), "r"(a[3]), "r"(b[0]), "r"(b[1]));
}

__device__ __forceinline__ void cp_async16(void* smem, const void* gmem) {
    uint32_t s = (uint32_t)__cvta_generic_to_shared(smem);
    asm volatile("cp.async.cg.shared.global [%0], [%1], 16;" :: "r"(s), "l"(gmem));
}
__device__ __forceinline__ void cp_commit() {
    asm volatile("cp.async.commit_group;" ::: "memory");
}
template <int N>
__device__ __forceinline__ void cp_wait() {
    asm volatile("cp.async.wait_group %0;" :: "n"(N) : "memory");
}

// ---------------- fused pre-round fp32 -> tf32 (5 tensors, 1 launch) --------
__global__ void round_all_kernel(
    float* d0, const float* s0, float* d1, const float* s1,
    float* d2, const float* s2, float* d3, const float* s3,
    float* d4, const float* s4)
{
    // region sizes in float4: 4194304, 4194304, 1048576, 1048576, 4194304
    long long i = (long long)blockIdx.x * blockDim.x + threadIdx.x;
    const float* src;
    float* dst;
    long long off;
    if (i < 4194304)        { src = s0; dst = d0; off = i; }
    else if (i < 8388608)   { src = s1; dst = d1; off = i - 4194304; }
    else if (i < 9437184)   { src = s2; dst = d2; off = i - 8388608; }
    else if (i < 10485760)  { src = s3; dst = d3; off = i - 9437184; }
    else                    { src = s4; dst = d4; off = i - 10485760; }
    float4 v = ((const float4*)src)[off];
    v.x = __uint_as_float(f2tf32(v.x));
    v.y = __uint_as_float(f2tf32(v.y));
    v.z = __uint_as_float(f2tf32(v.z));
    v.w = __uint_as_float(f2tf32(v.w));
    ((float4*)dst)[off] = v;
}

// ---------------- TF32 GEMM: C[M,N] = A[M,K] * B[N,K]^T  --------------------
// CTA 128x128, 4 warps of 64x64. BK=32 per stage, 3-stage cp.async pipeline.
// Smem: per stage, A and B each stored as 2 panels of [128][16] floats
// (LD=16 == 16 mod 32 -> conflict-free LDS.128 with k-slots {4t..4t+3}).
// One LDS.128 feeds fragments of TWO m16n8k8 MMAs (same k-bijection on A & B).
#define GSTG_FL 8192                  // floats per stage (A 4096 + B 4096)
#define GSMEM_BYTES (3 * GSTG_FL * 4) // 98304

__global__ __launch_bounds__(128, 2) void gemm_tf32(
    float* __restrict__ C, const float* __restrict__ A, const float* __restrict__ B,
    int N, int K, int roundOut)
{
    extern __shared__ float smem[];

    const int bm = blockIdx.y * 128;
    const int bn = blockIdx.x * 128;
    const int tid = threadIdx.x;
    const int warp = tid >> 5, lane = tid & 31;
    const int wm = (warp & 1) << 6;   // 0,64
    const int wn = (warp >> 1) << 6;  // 0,64
    const int g = lane >> 2, t = lane & 3;

    float acc[4][8][4];
#pragma unroll
    for (int a = 0; a < 4; ++a)
#pragma unroll
        for (int b = 0; b < 8; ++b)
#pragma unroll
            for (int c = 0; c < 4; ++c) acc[a][b][c] = 0.f;

    // per stage: A rows bm..+127 cols k0..+31 -> panels [kk][row][16]
    auto load_stage = [&](int s, int k0) {
        float* SA = smem + s * GSTG_FL;
        float* SB = SA + 4096;
#pragma unroll
        for (int i = 0; i < 8; ++i) {
            int c = tid + (i << 7);        // 0..1023
            int row = c >> 3;              // 0..127
            int cc = c & 7;                // 16B chunk in row (8 per 32-float row)
            int kk = cc >> 2, c4 = cc & 3;
            cp_async16(SA + ((kk << 7) + row) * 16 + (c4 << 2),
                       A + (size_t)(bm + row) * K + k0 + (cc << 2));
        }
#pragma unroll
        for (int i = 0; i < 8; ++i) {
            int c = tid + (i << 7);
            int row = c >> 3;
            int cc = c & 7;
            int kk = cc >> 2, c4 = cc & 3;
            cp_async16(SB + ((kk << 7) + row) * 16 + (c4 << 2),
                       B + (size_t)(bn + row) * K + k0 + (cc << 2));
        }
    };

    const int nIter = K >> 5;   // K/32
    load_stage(0, 0); cp_commit();
    load_stage(1, 32); cp_commit();

    int slot = 0;
    for (int it = 0; it < nIter; ++it) {
        cp_wait<1>();
        __syncthreads();
        if (it + 2 < nIter) {
            int ns = slot + 2; if (ns >= 3) ns -= 3;
            load_stage(ns, (it + 2) << 5);
            cp_commit();
        }
        const float* SA = smem + slot * GSTG_FL;
        const float* SB = SA + 4096;

#pragma unroll
        for (int kk = 0; kk < 2; ++kk) {
            float4 a0[4], a1[4];
#pragma unroll
            for (int mt = 0; mt < 4; ++mt) {
                int r = wm + (mt << 4) + g;
                a0[mt] = *(const float4*)&SA[((kk << 7) + r) * 16 + (t << 2)];
                a1[mt] = *(const float4*)&SA[((kk << 7) + r + 8) * 16 + (t << 2)];
            }
#pragma unroll
            for (int nt = 0; nt < 8; ++nt) {
                float4 b = *(const float4*)&SB[((kk << 7) + wn + (nt << 3) + g) * 16 + (t << 2)];
                uint32_t bf0[2] = {fu(b.x), fu(b.y)};
                uint32_t bf1[2] = {fu(b.z), fu(b.w)};
#pragma unroll
                for (int mt = 0; mt < 4; ++mt) {
                    uint32_t af0[4] = {fu(a0[mt].x), fu(a1[mt].x), fu(a0[mt].y), fu(a1[mt].y)};
                    mma_tf32(acc[mt][nt], af0, bf0);
                    uint32_t af1[4] = {fu(a0[mt].z), fu(a1[mt].z), fu(a0[mt].w), fu(a1[mt].w)};
                    mma_tf32(acc[mt][nt], af1, bf1);
                }
            }
        }
        if (++slot == 3) slot = 0;
    }

    // epilogue
#pragma unroll
    for (int mt = 0; mt < 4; ++mt) {
        int r0 = bm + wm + (mt << 4) + g;
#pragma unroll
        for (int nt = 0; nt < 8; ++nt) {
            int cc = bn + wn + (nt << 3) + 2 * t;
            float2 v0 = make_float2(acc[mt][nt][0], acc[mt][nt][1]);
            float2 v1 = make_float2(acc[mt][nt][2], acc[mt][nt][3]);
            if (roundOut) {
                v0.x = __uint_as_float(f2tf32(v0.x));
                v0.y = __uint_as_float(f2tf32(v0.y));
                v1.x = __uint_as_float(f2tf32(v1.x));
                v1.y = __uint_as_float(f2tf32(v1.y));
            }
            *(float2*)&C[(size_t)r0 * N + cc] = v0;
            *(float2*)&C[(size_t)(r0 + 8) * N + cc] = v1;
        }
    }
}

// ---------------- RoPE (interleaved pairs), in-place, rounds to tf32 --------
__global__ void rope_kernel(float* __restrict__ x, const float* __restrict__ cs,
                            const float* __restrict__ sn, int nheads)
{
    int idx = blockIdx.x * blockDim.x + threadIdx.x;
    int total = 4096 * nheads * 64;
    if (idx >= total) return;
    int i = idx & 63;
    int h = (idx >> 6) % nheads;
    int tok = idx / (64 * nheads);
    int s = tok & 2047;
    float c = cs[s * 64 + i];
    float si = sn[s * 64 + i];
    float2* p = (float2*)(x + ((size_t)tok * nheads + h) * 128) + i;
    float2 v = *p;
    *p = make_float2(__uint_as_float(f2tf32(v.x * c - v.y * si)),
                     __uint_as_float(f2tf32(v.x * si + v.y * c)));
}

// ---------------- causal GQA flash attention --------------------------------
#define QT 64
#define KT 32
#define LQS 152
#define LKS 152
#define LVS 136

__global__ __launch_bounds__(128) void attn_kernel(
    float* __restrict__ O, const float* __restrict__ Q,
    const float* __restrict__ Kg, const float* __restrict__ Vg)
{
    __shared__ float sbuf[QT * LQS];
    float* Ks = sbuf;
    float* Vs = sbuf + KT * LKS;

    const int qtile = blockIdx.x;
    const int h = blockIdx.y;
    const int b = blockIdx.z;
    const int kvh = h >> 2;
    const int tid = threadIdx.x;
    const int warp = tid >> 5, lane = tid & 31;
    const int g = lane >> 2, t = lane & 3;
    const int q0 = qtile * QT;

    const float qscale = 0.08838834764831845f * 1.4426950408889634f;

    {
        float* Qs = sbuf;
#pragma unroll
        for (int pass = 0; pass < 16; ++pass) {
            int r = pass * 4 + (tid >> 5);
            int c = (tid & 31) << 2;
            float4 v = *(const float4*)&Q[(size_t)(b * 2048 + q0 + r) * 4096 + h * 128 + c];
            Qs[r * LQS + c + 0] = __uint_as_float(f2tf32(v.x * qscale));
            Qs[r * LQS + c + 1] = __uint_as_float(f2tf32(v.y * qscale));
            Qs[r * LQS + c + 2] = __uint_as_float(f2tf32(v.z * qscale));
            Qs[r * LQS + c + 3] = __uint_as_float(f2tf32(v.w * qscale));
        }
    }
    __syncthreads();

    uint32_t qf[16][4];
    {
        const float* Qs = sbuf;
        int r = warp * 16;
#pragma unroll
        for (int kc = 0; kc < 16; ++kc) {
            float2 p0 = *(const float2*)&Qs[(r + g) * LQS + kc * 8 + 2 * t];
            float2 p1 = *(const float2*)&Qs[(r + g + 8) * LQS + kc * 8 + 2 * t];
            qf[kc][0] = fu(p0.x);
            qf[kc][1] = fu(p1.x);
            qf[kc][2] = fu(p0.y);
            qf[kc][3] = fu(p1.y);
        }
    }
    __syncthreads();

    float o[16][4];
#pragma unroll
    for (int i = 0; i < 16; ++i)
#pragma unroll
        for (int j = 0; j < 4; ++j) o[i][j] = 0.f;

    float m0 = -CUDART_INF_F, m1 = -CUDART_INF_F, l0 = 0.f, l1 = 0.f;
    const int rowg0 = q0 + warp * 16 + g;
    const int rowg1 = rowg0 + 8;

    const int src1 = (lane & 28) | (t >> 1);
    const int src2 = src1 | 2;
    const bool odd = (t & 1);

    for (int kv0 = 0; kv0 < q0 + QT; kv0 += KT) {
#pragma unroll
        for (int pass = 0; pass < 8; ++pass) {
            int r = pass * 4 + (tid >> 5);
            int c = (tid & 31) << 2;
            size_t gidx = (size_t)(b * 2048 + kv0 + r) * 1024 + kvh * 128 + c;
            *(float4*)&Ks[r * LKS + c] = *(const float4*)&Kg[gidx];
            *(float4*)&Vs[r * LVS + c] = *(const float4*)&Vg[gidx];
        }
        __syncthreads();

        float sv[4][4];
#pragma unroll
        for (int nt = 0; nt < 4; ++nt)
#pragma unroll
            for (int j = 0; j < 4; ++j) sv[nt][j] = 0.f;

#pragma unroll
        for (int kc = 0; kc < 16; ++kc) {
            const int kcol = kc * 8 + 2 * t;
#pragma unroll
            for (int nt = 0; nt < 4; ++nt) {
                float2 kb = *(const float2*)&Ks[(nt * 8 + g) * LKS + kcol];
                uint32_t bf[2] = {fu(kb.x), fu(kb.y)};
                mma_tf32(sv[nt], qf[kc], bf);
            }
        }

        if (kv0 + KT > q0) {
#pragma unroll
            for (int nt = 0; nt < 4; ++nt) {
                int c0 = kv0 + nt * 8 + 2 * t;
                if (c0 > rowg0) sv[nt][0] = -CUDART_INF_F;
                if (c0 + 1 > rowg0) sv[nt][1] = -CUDART_INF_F;
                if (c0 > rowg1) sv[nt][2] = -CUDART_INF_F;
                if (c0 + 1 > rowg1) sv[nt][3] = -CUDART_INF_F;
            }
        }

        float mx0 = -CUDART_INF_F, mx1 = -CUDART_INF_F;
#pragma unroll
        for (int nt = 0; nt < 4; ++nt) {
            mx0 = fmaxf(mx0, fmaxf(sv[nt][0], sv[nt][1]));
            mx1 = fmaxf(mx1, fmaxf(sv[nt][2], sv[nt][3]));
        }
        mx0 = fmaxf(mx0, __shfl_xor_sync(FULLMASK, mx0, 1));
        mx0 = fmaxf(mx0, __shfl_xor_sync(FULLMASK, mx0, 2));
        mx1 = fmaxf(mx1, __shfl_xor_sync(FULLMASK, mx1, 1));
        mx1 = fmaxf(mx1, __shfl_xor_sync(FULLMASK, mx1, 2));

        float nm0 = fmaxf(m0, mx0), nm1 = fmaxf(m1, mx1);
        float a0 = exp2f(m0 - nm0), a1 = exp2f(m1 - nm1);
        m0 = nm0; m1 = nm1;

        float rs0 = 0.f, rs1 = 0.f;
#pragma unroll
        for (int nt = 0; nt < 4; ++nt) {
            sv[nt][0] = exp2f(sv[nt][0] - m0);
            sv[nt][1] = exp2f(sv[nt][1] - m0);
            sv[nt][2] = exp2f(sv[nt][2] - m1);
            sv[nt][3] = exp2f(sv[nt][3] - m1);
            rs0 += sv[nt][0] + sv[nt][1];
            rs1 += sv[nt][2] + sv[nt][3];
        }
        rs0 += __shfl_xor_sync(FULLMASK, rs0, 1);
        rs0 += __shfl_xor_sync(FULLMASK, rs0, 2);
        rs1 += __shfl_xor_sync(FULLMASK, rs1, 1);
        rs1 += __shfl_xor_sync(FULLMASK, rs1, 2);
        l0 = l0 * a0 + rs0;
        l1 = l1 * a1 + rs1;

#pragma unroll
        for (int ht = 0; ht < 16; ++ht) {
            o[ht][0] *= a0; o[ht][1] *= a0;
            o[ht][2] *= a1; o[ht][3] *= a1;
        }

#pragma unroll
        for (int kc = 0; kc < 4; ++kc) {
            float x0 = __shfl_sync(FULLMASK, sv[kc][0], src1);
            float x1 = __shfl_sync(FULLMASK, sv[kc][1], src1);
            float x2 = __shfl_sync(FULLMASK, sv[kc][2], src1);
            float x3 = __shfl_sync(FULLMASK, sv[kc][3], src1);
            float y0 = __shfl_sync(FULLMASK, sv[kc][0], src2);
            float y1 = __shfl_sync(FULLMASK, sv[kc][1], src2);
            float y2 = __shfl_sync(FULLMASK, sv[kc][2], src2);
            float y3 = __shfl_sync(FULLMASK, sv[kc][3], src2);
            uint32_t af[4];
            af[0] = f2tf32(odd ? x1 : x0);
            af[1] = f2tf32(odd ? x3 : x2);
            af[2] = f2tf32(odd ? y1 : y0);
            af[3] = f2tf32(odd ? y3 : y2);
#pragma unroll
            for (int ht = 0; ht < 16; ++ht) {
                uint32_t bf[2];
                bf[0] = fu(Vs[(kc * 8 + t) * LVS + ht * 8 + g]);
                bf[1] = fu(Vs[(kc * 8 + t + 4) * LVS + ht * 8 + g]);
                mma_tf32(o[ht], af, bf);
            }
        }
        __syncthreads();
    }

    float i0 = 1.f / l0, i1 = 1.f / l1;
#pragma unroll
    for (int ht = 0; ht < 16; ++ht) {
        size_t base = (size_t)(b * 2048 + rowg0) * 4096 + h * 128 + ht * 8 + 2 * t;
        *(float2*)&O[base] = make_float2(__uint_as_float(f2tf32(o[ht][0] * i0)),
                                         __uint_as_float(f2tf32(o[ht][1] * i0)));
        *(float2*)&O[base + (size_t)8 * 4096] =
            make_float2(__uint_as_float(f2tf32(o[ht][2] * i1)),
                        __uint_as_float(f2tf32(o[ht][3] * i1)));
    }
}

// ---------------- entry -----------------------------------------------------
extern "C" void kernel_launch(void* const* d_in, const int* in_sizes, int n_in,
                              void* d_out, int out_size)
{
    const float* x  = (const float*)d_in[0];
    const float* wq = (const float*)d_in[1];
    const float* wk = (const float*)d_in[2];
    const float* wv = (const float*)d_in[3];
    const float* wo = (const float*)d_in[4];
    const float* fc = (const float*)d_in[5];
    const float* fs = (const float*)d_in[6];
    float* out = (float*)d_out;

    float *gxr, *gwqr, *gwkr, *gwvr, *gwor, *gq, *gk, *gv, *ga;
    cudaGetSymbolAddress((void**)&gxr,  g_xr);
    cudaGetSymbolAddress((void**)&gwqr, g_wqr);
    cudaGetSymbolAddress((void**)&gwkr, g_wkr);
    cudaGetSymbolAddress((void**)&gwvr, g_wvr);
    cudaGetSymbolAddress((void**)&gwor, g_wor);
    cudaGetSymbolAddress((void**)&gq, g_q);
    cudaGetSymbolAddress((void**)&gk, g_k);
    cudaGetSymbolAddress((void**)&gv, g_v);
    cudaGetSymbolAddress((void**)&ga, g_att);

    cudaFuncSetAttribute(gemm_tf32, cudaFuncAttributeMaxDynamicSharedMemorySize, GSMEM_BYTES);

    // launch 1: fused rounding of all GEMM inputs (14,680,064 float4)
    round_all_kernel<<<57344, 256>>>(gxr, x, gwqr, wq, gwkr, wk, gwvr, wv, gwor, wo);

    // launches 2-4: K, V (rounded out), ropeK
    gemm_tf32<<<dim3(8, 32),  128, GSMEM_BYTES>>>(gk, gxr, gwkr, 1024, 4096, 0);
    gemm_tf32<<<dim3(8, 32),  128, GSMEM_BYTES>>>(gv, gxr, gwvr, 1024, 4096, 1);
    rope_kernel<<<(4096 * 8 * 64 + 255) / 256, 256>>>(gk, fc, fs, 8);

    // launch 5 (profiled slot): the big Q projection
    gemm_tf32<<<dim3(32, 32), 128, GSMEM_BYTES>>>(gq, gxr, gwqr, 4096, 4096, 0);

    rope_kernel<<<(4096 * 32 * 64 + 255) / 256, 256>>>(gq, fc, fs, 32);

    attn_kernel<<<dim3(32, 32, 2), 128>>>(ga, gq, gk, gv);

    gemm_tf32<<<dim3(32, 32), 128, GSMEM_BYTES>>>(out, ga, gwor, 4096, 4096, 0);
}

// round 6
// speedup vs baseline: 2.2699x; 1.8705x over previous
#include <cuda_runtime.h>
#include <cuda_fp16.h>
#include <cstdint>
#include <math_constants.h>

#define FULLMASK 0xffffffffu

// ---------------- scratch (static device arrays; no cudaMalloc) -------------
static __device__ __half g_xh [4096u * 4096u];  // x  -> half
static __device__ __half g_wqh[4096u * 4096u];
static __device__ __half g_wkh[1024u * 4096u];
static __device__ __half g_wvh[1024u * 4096u];
static __device__ __half g_woh[4096u * 4096u];
static __device__ __half g_q  [4096u * 4096u];  // xq (roped)
static __device__ __half g_k  [4096u * 1024u];  // xk (roped)
static __device__ __half g_vt [1024u * 4096u];  // xv TRANSPOSED: [hd_global][token]
static __device__ __half g_att[4096u * 4096u];  // attention out

// ---------------- helpers ---------------------------------------------------
__device__ __forceinline__ void mma_f16(float* c, uint32_t a0, uint32_t a1,
                                        uint32_t a2, uint32_t a3,
                                        uint32_t b0, uint32_t b1) {
    asm volatile(
        "mma.sync.aligned.m16n8k16.row.col.f32.f16.f16.f32 "
        "{%0,%1,%2,%3}, {%4,%5,%6,%7}, {%8,%9}, {%0,%1,%2,%3};"
        : "+f"(c[0]), "+f"(c[1]), "+f"(c[2]), "+f"(c[3])
        : "r"(a0), "r"(a1), "r"(a2), "r"(a3), "r"(b0), "r"(b1));
}

__device__ __forceinline__ void cp_async16(void* smem, const void* gmem) {
    uint32_t s = (uint32_t)__cvta_generic_to_shared(smem);
    asm volatile("cp.async.cg.shared.global [%0], [%1], 16;" :: "r"(s), "l"(gmem));
}
__device__ __forceinline__ void cp_commit() {
    asm volatile("cp.async.commit_group;" ::: "memory");
}
template <int N>
__device__ __forceinline__ void cp_wait() {
    asm volatile("cp.async.wait_group %0;" :: "n"(N) : "memory");
}
__device__ __forceinline__ uint32_t h2u(__half2 h) { return *(uint32_t*)&h; }

// ---------------- fused fp32 -> fp16 convert (5 tensors, 1 launch) ----------
__global__ void conv_all_kernel(
    __half* d0, const float* s0, __half* d1, const float* s1,
    __half* d2, const float* s2, __half* d3, const float* s3,
    __half* d4, const float* s4)
{
    // sizes in 8-float units: 2097152, 2097152, 524288, 524288, 2097152
    long long i = (long long)blockIdx.x * blockDim.x + threadIdx.x;
    const float* src; __half* dst; long long off;
    if (i < 2097152)      { src = s0; dst = d0; off = i; }
    else if (i < 4194304) { src = s1; dst = d1; off = i - 2097152; }
    else if (i < 4718592) { src = s2; dst = d2; off = i - 4194304; }
    else if (i < 5242880) { src = s3; dst = d3; off = i - 4718592; }
    else                  { src = s4; dst = d4; off = i - 5242880; }
    float4 v0 = ((const float4*)src)[2 * off];
    float4 v1 = ((const float4*)src)[2 * off + 1];
    __half2 h0 = __floats2half2_rn(v0.x, v0.y);
    __half2 h1 = __floats2half2_rn(v0.z, v0.w);
    __half2 h2 = __floats2half2_rn(v1.x, v1.y);
    __half2 h3 = __floats2half2_rn(v1.z, v1.w);
    uint4 o = make_uint4(h2u(h0), h2u(h1), h2u(h2), h2u(h3));
    ((uint4*)dst)[off] = o;
}

// ---------------- FP16 GEMM: C[M,N] = A[M,K] * B[N,K]^T  --------------------
// CTA 128x128, 4 warps of 64x64, BK=32, 4-stage cp.async pipeline.
// Smem rows = 32 halves (64B); k-slot bijection: thread t's LDS.128 covers
// halves 8t..8t+7 -> feeds 2 m16n8k16 MMAs. Conflict-free loads & stores.
// MODE: 0 = half out, 1 = half out TRANSPOSED (C^T[N][ldc]), 2 = float out.
#define GST 16384
#define GSMEM_BYTES (4 * GST)   // 65536

template <int MODE>
__global__ __launch_bounds__(128, 2) void gemm_f16(
    void* Cp, const __half* __restrict__ A, const __half* __restrict__ B,
    int K, int ldc)
{
    extern __shared__ char smem[];
    const int bm = blockIdx.y * 128, bn = blockIdx.x * 128;
    const int tid = threadIdx.x;
    const int warp = tid >> 5, lane = tid & 31;
    const int wm = (warp & 1) << 6, wn = (warp >> 1) << 6;
    const int g = lane >> 2, t = lane & 3;

    float acc[4][8][4];
#pragma unroll
    for (int a = 0; a < 4; ++a)
#pragma unroll
        for (int b = 0; b < 8; ++b)
#pragma unroll
            for (int c = 0; c < 4; ++c) acc[a][b][c] = 0.f;

    auto load_stage = [&](int s, int k0) {
        char* SA = smem + s * GST;
        char* SB = SA + 8192;
#pragma unroll
        for (int i = 0; i < 4; ++i) {
            int c = tid + (i << 7);   // 0..511
            int row = c >> 2, sub = c & 3;
            cp_async16(SA + row * 64 + sub * 16, A + (size_t)(bm + row) * K + k0 + sub * 8);
        }
#pragma unroll
        for (int i = 0; i < 4; ++i) {
            int c = tid + (i << 7);
            int row = c >> 2, sub = c & 3;
            cp_async16(SB + row * 64 + sub * 16, B + (size_t)(bn + row) * K + k0 + sub * 8);
        }
    };

    const int nIter = K >> 5;
    load_stage(0, 0);  cp_commit();
    load_stage(1, 32); cp_commit();
    load_stage(2, 64); cp_commit();

    for (int it = 0; it < nIter; ++it) {
        cp_wait<2>();
        __syncthreads();
        if (it + 3 < nIter) { load_stage((it + 3) & 3, (it + 3) << 5); cp_commit(); }

        const char* SA = smem + (it & 3) * GST;
        const char* SB = SA + 8192;

        uint4 af[4][2];
#pragma unroll
        for (int mt = 0; mt < 4; ++mt) {
            af[mt][0] = *(const uint4*)(SA + (wm + (mt << 4) + g) * 64 + (t << 4));
            af[mt][1] = *(const uint4*)(SA + (wm + (mt << 4) + 8 + g) * 64 + (t << 4));
        }
#pragma unroll
        for (int nt = 0; nt < 8; ++nt) {
            uint4 bf = *(const uint4*)(SB + (wn + (nt << 3) + g) * 64 + (t << 4));
#pragma unroll
            for (int mt = 0; mt < 4; ++mt) {
                mma_f16(acc[mt][nt], af[mt][0].x, af[mt][1].x, af[mt][0].y, af[mt][1].y, bf.x, bf.y);
                mma_f16(acc[mt][nt], af[mt][0].z, af[mt][1].z, af[mt][0].w, af[mt][1].w, bf.z, bf.w);
            }
        }
    }

#pragma unroll
    for (int mt = 0; mt < 4; ++mt) {
        int r0 = bm + wm + (mt << 4) + g;
#pragma unroll
        for (int nt = 0; nt < 8; ++nt) {
            int c0 = bn + wn + (nt << 3) + 2 * t;
            if (MODE == 2) {
                float* C = (float*)Cp;
                *(float2*)&C[(size_t)r0 * ldc + c0] = make_float2(acc[mt][nt][0], acc[mt][nt][1]);
                *(float2*)&C[(size_t)(r0 + 8) * ldc + c0] = make_float2(acc[mt][nt][2], acc[mt][nt][3]);
            } else if (MODE == 0) {
                __half* C = (__half*)Cp;
                *(__half2*)&C[(size_t)r0 * ldc + c0] = __floats2half2_rn(acc[mt][nt][0], acc[mt][nt][1]);
                *(__half2*)&C[(size_t)(r0 + 8) * ldc + c0] = __floats2half2_rn(acc[mt][nt][2], acc[mt][nt][3]);
            } else {
                __half* C = (__half*)Cp;
                C[(size_t)c0 * ldc + r0]           = __float2half_rn(acc[mt][nt][0]);
                C[(size_t)(c0 + 1) * ldc + r0]     = __float2half_rn(acc[mt][nt][1]);
                C[(size_t)c0 * ldc + r0 + 8]       = __float2half_rn(acc[mt][nt][2]);
                C[(size_t)(c0 + 1) * ldc + r0 + 8] = __float2half_rn(acc[mt][nt][3]);
            }
        }
    }
}

// ---------------- RoPE on half, in-place ------------------------------------
__global__ void rope_kernel(__half* __restrict__ x, const float* __restrict__ cs,
                            const float* __restrict__ sn, int nheads)
{
    int idx = blockIdx.x * blockDim.x + threadIdx.x;
    int total = 4096 * nheads * 64;
    if (idx >= total) return;
    int i = idx & 63;
    int h = (idx >> 6) % nheads;
    int tok = idx / (64 * nheads);
    int s = tok & 2047;
    float c = cs[s * 64 + i];
    float si = sn[s * 64 + i];
    __half2* p = (__half2*)(x + ((size_t)tok * nheads + h) * 128) + i;
    float2 v = __half22float2(*p);
    *p = __floats2half2_rn(v.x * c - v.y * si, v.x * si + v.y * c);
}

// ---------------- causal GQA flash attention (fp16 mma) ---------------------
#define QT 64
#define KT 32
#define QSTR 160   // halves; 320B row stride -> conflict-free LDS.128 frags
#define VSTR 40    // halves; 80B row stride  -> conflict-free LDS.32 b-frags

__global__ __launch_bounds__(128) void attn_kernel(
    __half* __restrict__ O, const __half* __restrict__ Q,
    const __half* __restrict__ Kg, const __half* __restrict__ Vtg)
{
    __shared__ __align__(16) __half Qs[64 * QSTR];   // 20480 B
    __shared__ __align__(16) __half Ks[32 * QSTR];   // 10240 B
    __shared__ __align__(16) __half Vs[128 * VSTR];  // 10240 B

    const int qtile = blockIdx.x;
    const int h = blockIdx.y;
    const int b = blockIdx.z;
    const int kvh = h >> 2;
    const int tid = threadIdx.x;
    const int warp = tid >> 5, lane = tid & 31;
    const int g = lane >> 2, t = lane & 3;
    const int q0 = qtile * QT;

    const float qscale = 0.08838834764831845f * 1.4426950408889634f;

    // stage Q (scaled), 64 rows x 128 halves = 1024 uint4
#pragma unroll
    for (int j = 0; j < 8; ++j) {
        int c = tid + (j << 7);           // 0..1023
        int row = c >> 4, sub = c & 15;
        uint4 v = *(const uint4*)&Q[(size_t)(b * 2048 + q0 + row) * 4096 + h * 128 + sub * 8];
        __half2* hp = (__half2*)&v;
#pragma unroll
        for (int e = 0; e < 4; ++e) {
            float2 f = __half22float2(hp[e]);
            hp[e] = __floats2half2_rn(f.x * qscale, f.y * qscale);
        }
        *(uint4*)&Qs[row * QSTR + sub * 8] = v;
    }
    __syncthreads();

    // per-warp Q fragments: 4 k32-chunks x (rows g, g+8)
    uint4 qf[4][2];
    {
        int r = warp * 16;
#pragma unroll
        for (int c = 0; c < 4; ++c) {
            qf[c][0] = *(const uint4*)&Qs[(r + g) * QSTR + c * 32 + t * 8];
            qf[c][1] = *(const uint4*)&Qs[(r + g + 8) * QSTR + c * 32 + t * 8];
        }
    }
    __syncthreads();

    float o[16][4];
#pragma unroll
    for (int i = 0; i < 16; ++i)
#pragma unroll
        for (int j = 0; j < 4; ++j) o[i][j] = 0.f;

    float m0 = -CUDART_INF_F, m1 = -CUDART_INF_F, l0 = 0.f, l1 = 0.f;
    const int rowg0 = q0 + warp * 16 + g;
    const int rowg1 = rowg0 + 8;

    for (int kv0 = 0; kv0 < q0 + QT; kv0 += KT) {
        // stage K [32][128] and Vt [128][32]
#pragma unroll
        for (int j = 0; j < 4; ++j) {
            int c = tid + (j << 7);          // 0..511
            int row = c >> 4, sub = c & 15;
            *(uint4*)&Ks[row * QSTR + sub * 8] =
                *(const uint4*)&Kg[(size_t)(b * 2048 + kv0 + row) * 1024 + kvh * 128 + sub * 8];
        }
#pragma unroll
        for (int j = 0; j < 4; ++j) {
            int c = tid + (j << 7);
            int row = c >> 2, sub = c & 3;
            *(uint4*)&Vs[row * VSTR + sub * 8] =
                *(const uint4*)&Vtg[(size_t)(kvh * 128 + row) * 4096 + b * 2048 + kv0 + sub * 8];
        }
        __syncthreads();

        // S = Q * K^T  (m16 x n32, k=128)
        float sv[4][4];
#pragma unroll
        for (int nt = 0; nt < 4; ++nt)
#pragma unroll
            for (int j = 0; j < 4; ++j) sv[nt][j] = 0.f;

#pragma unroll
        for (int c = 0; c < 4; ++c) {
#pragma unroll
            for (int nt = 0; nt < 4; ++nt) {
                uint4 kf = *(const uint4*)&Ks[(nt * 8 + g) * QSTR + c * 32 + t * 8];
                mma_f16(sv[nt], qf[c][0].x, qf[c][1].x, qf[c][0].y, qf[c][1].y, kf.x, kf.y);
                mma_f16(sv[nt], qf[c][0].z, qf[c][1].z, qf[c][0].w, qf[c][1].w, kf.z, kf.w);
            }
        }

        // causal mask
        if (kv0 + KT > q0) {
#pragma unroll
            for (int nt = 0; nt < 4; ++nt) {
                int c0 = kv0 + nt * 8 + 2 * t;
                if (c0 > rowg0) sv[nt][0] = -CUDART_INF_F;
                if (c0 + 1 > rowg0) sv[nt][1] = -CUDART_INF_F;
                if (c0 > rowg1) sv[nt][2] = -CUDART_INF_F;
                if (c0 + 1 > rowg1) sv[nt][3] = -CUDART_INF_F;
            }
        }

        // online softmax (rows within warp)
        float mx0 = -CUDART_INF_F, mx1 = -CUDART_INF_F;
#pragma unroll
        for (int nt = 0; nt < 4; ++nt) {
            mx0 = fmaxf(mx0, fmaxf(sv[nt][0], sv[nt][1]));
            mx1 = fmaxf(mx1, fmaxf(sv[nt][2], sv[nt][3]));
        }
        mx0 = fmaxf(mx0, __shfl_xor_sync(FULLMASK, mx0, 1));
        mx0 = fmaxf(mx0, __shfl_xor_sync(FULLMASK, mx0, 2));
        mx1 = fmaxf(mx1, __shfl_xor_sync(FULLMASK, mx1, 1));
        mx1 = fmaxf(mx1, __shfl_xor_sync(FULLMASK, mx1, 2));

        float nm0 = fmaxf(m0, mx0), nm1 = fmaxf(m1, mx1);
        float a0 = exp2f(m0 - nm0), a1 = exp2f(m1 - nm1);
        m0 = nm0; m1 = nm1;

        float rs0 = 0.f, rs1 = 0.f;
#pragma unroll
        for (int nt = 0; nt < 4; ++nt) {
            sv[nt][0] = exp2f(sv[nt][0] - m0);
            sv[nt][1] = exp2f(sv[nt][1] - m0);
            sv[nt][2] = exp2f(sv[nt][2] - m1);
            sv[nt][3] = exp2f(sv[nt][3] - m1);
            rs0 += sv[nt][0] + sv[nt][1];
            rs1 += sv[nt][2] + sv[nt][3];
        }
        rs0 += __shfl_xor_sync(FULLMASK, rs0, 1);
        rs0 += __shfl_xor_sync(FULLMASK, rs0, 2);
        rs1 += __shfl_xor_sync(FULLMASK, rs1, 1);
        rs1 += __shfl_xor_sync(FULLMASK, rs1, 2);
        l0 = l0 * a0 + rs0;
        l1 = l1 * a1 + rs1;

#pragma unroll
        for (int ht = 0; ht < 16; ++ht) {
            o[ht][0] *= a0; o[ht][1] *= a0;
            o[ht][2] *= a1; o[ht][3] *= a1;
        }

        // P: C-frag layout == A-frag layout for m16n8k16 -> no shuffles
        uint32_t p00 = h2u(__floats2half2_rn(sv[0][0], sv[0][1]));
        uint32_t p01 = h2u(__floats2half2_rn(sv[0][2], sv[0][3]));
        uint32_t p02 = h2u(__floats2half2_rn(sv[1][0], sv[1][1]));
        uint32_t p03 = h2u(__floats2half2_rn(sv[1][2], sv[1][3]));
        uint32_t p10 = h2u(__floats2half2_rn(sv[2][0], sv[2][1]));
        uint32_t p11 = h2u(__floats2half2_rn(sv[2][2], sv[2][3]));
        uint32_t p12 = h2u(__floats2half2_rn(sv[3][0], sv[3][1]));
        uint32_t p13 = h2u(__floats2half2_rn(sv[3][2], sv[3][3]));

        // O += P * V  (V^T in smem: rows = hd, cols = kv)
#pragma unroll
        for (int ht = 0; ht < 16; ++ht) {
            const __half* vr = &Vs[(8 * ht + g) * VSTR];
            uint32_t b0 = *(const uint32_t*)(vr + 2 * t);
            uint32_t b1 = *(const uint32_t*)(vr + 2 * t + 8);
            mma_f16(o[ht], p00, p01, p02, p03, b0, b1);
            uint32_t b2 = *(const uint32_t*)(vr + 16 + 2 * t);
            uint32_t b3 = *(const uint32_t*)(vr + 16 + 2 * t + 8);
            mma_f16(o[ht], p10, p11, p12, p13, b2, b3);
        }
        __syncthreads();
    }

    // epilogue: normalize, store half
    float i0 = 1.f / l0, i1 = 1.f / l1;
#pragma unroll
    for (int ht = 0; ht < 16; ++ht) {
        size_t base = (size_t)(b * 2048 + rowg0) * 4096 + h * 128 + 8 * ht + 2 * t;
        *(__half2*)&O[base] = __floats2half2_rn(o[ht][0] * i0, o[ht][1] * i0);
        *(__half2*)&O[base + (size_t)8 * 4096] = __floats2half2_rn(o[ht][2] * i1, o[ht][3] * i1);
    }
}

// ---------------- entry -----------------------------------------------------
extern "C" void kernel_launch(void* const* d_in, const int* in_sizes, int n_in,
                              void* d_out, int out_size)
{
    const float* x  = (const float*)d_in[0];
    const float* wq = (const float*)d_in[1];
    const float* wk = (const float*)d_in[2];
    const float* wv = (const float*)d_in[3];
    const float* wo = (const float*)d_in[4];
    const float* fc = (const float*)d_in[5];
    const float* fs = (const float*)d_in[6];
    float* out = (float*)d_out;

    __half *xh, *wqh, *wkh, *wvh, *woh, *q, *k, *vt, *att;
    cudaGetSymbolAddress((void**)&xh,  g_xh);
    cudaGetSymbolAddress((void**)&wqh, g_wqh);
    cudaGetSymbolAddress((void**)&wkh, g_wkh);
    cudaGetSymbolAddress((void**)&wvh, g_wvh);
    cudaGetSymbolAddress((void**)&woh, g_woh);
    cudaGetSymbolAddress((void**)&q,   g_q);
    cudaGetSymbolAddress((void**)&k,   g_k);
    cudaGetSymbolAddress((void**)&vt,  g_vt);
    cudaGetSymbolAddress((void**)&att, g_att);

    cudaFuncSetAttribute(gemm_f16<0>, cudaFuncAttributeMaxDynamicSharedMemorySize, GSMEM_BYTES);
    cudaFuncSetAttribute(gemm_f16<1>, cudaFuncAttributeMaxDynamicSharedMemorySize, GSMEM_BYTES);
    cudaFuncSetAttribute(gemm_f16<2>, cudaFuncAttributeMaxDynamicSharedMemorySize, GSMEM_BYTES);

    // 1: fused convert of all GEMM inputs to fp16
    conv_all_kernel<<<28672, 256>>>(xh, x, wqh, wq, wkh, wk, wvh, wv, woh, wo);

    // 2: V projection -> transposed half output g_vt [1024][4096]
    gemm_f16<1><<<dim3(8, 32), 128, GSMEM_BYTES>>>(vt, xh, wvh, 4096, 4096);

    // 3: K projection -> g_k [4096][1024]
    gemm_f16<0><<<dim3(8, 32), 128, GSMEM_BYTES>>>(k, xh, wkh, 4096, 1024);

    // 4 (profiled slot): Q projection -> g_q [4096][4096]
    gemm_f16<0><<<dim3(32, 32), 128, GSMEM_BYTES>>>(q, xh, wqh, 4096, 4096);

    // 5-6: RoPE on Q and K
    rope_kernel<<<(4096 * 32 * 64 + 255) / 256, 256>>>(q, fc, fs, 32);
    rope_kernel<<<(4096 * 8 * 64 + 255) / 256, 256>>>(k, fc, fs, 8);

    // 7: attention -> g_att (half)
    attn_kernel<<<dim3(32, 32, 2), 128>>>(att, q, k, vt);

    // 8: output projection -> d_out (fp32)
    gemm_f16<2><<<dim3(32, 32), 128, GSMEM_BYTES>>>(out, att, woh, 4096, 4096);
}

// round 7
// speedup vs baseline: 2.3343x; 1.0284x over previous
#include <cuda_runtime.h>
#include <cuda_fp16.h>
#include <cstdint>
#include <math_constants.h>

#define FULLMASK 0xffffffffu

// ---------------- scratch (static device arrays; no cudaMalloc) -------------
static __device__ __half g_xh [4096u * 4096u];  // x  -> half
static __device__ __half g_wqh[4096u * 4096u];
static __device__ __half g_wkh[1024u * 4096u];
static __device__ __half g_wvh[1024u * 4096u];
static __device__ __half g_woh[4096u * 4096u];
static __device__ __half g_q  [4096u * 4096u];  // xq (roped, pre-scaled)
static __device__ __half g_k  [4096u * 1024u];  // xk (roped)
static __device__ __half g_vt [1024u * 4096u];  // xv TRANSPOSED: [hd_global][token]
static __device__ __half g_att[4096u * 4096u];  // attention out

// ---------------- helpers ---------------------------------------------------
__device__ __forceinline__ void mma_f16(float* c, uint32_t a0, uint32_t a1,
                                        uint32_t a2, uint32_t a3,
                                        uint32_t b0, uint32_t b1) {
    asm volatile(
        "mma.sync.aligned.m16n8k16.row.col.f32.f16.f16.f32 "
        "{%0,%1,%2,%3}, {%4,%5,%6,%7}, {%8,%9}, {%0,%1,%2,%3};"
        : "+f"(c[0]), "+f"(c[1]), "+f"(c[2]), "+f"(c[3])
        : "r"(a0), "r"(a1), "r"(a2), "r"(a3), "r"(b0), "r"(b1));
}

__device__ __forceinline__ void cp_async16(void* smem, const void* gmem) {
    uint32_t s = (uint32_t)__cvta_generic_to_shared(smem);
    asm volatile("cp.async.cg.shared.global [%0], [%1], 16;" :: "r"(s), "l"(gmem));
}
__device__ __forceinline__ void cp_commit() {
    asm volatile("cp.async.commit_group;" ::: "memory");
}
template <int N>
__device__ __forceinline__ void cp_wait() {
    asm volatile("cp.async.wait_group %0;" :: "n"(N) : "memory");
}
__device__ __forceinline__ uint32_t h2u(__half2 h) { return *(uint32_t*)&h; }

// ---------------- fused fp32 -> fp16 convert (5 tensors, 1 launch) ----------
__global__ void conv_all_kernel(
    __half* d0, const float* s0, __half* d1, const float* s1,
    __half* d2, const float* s2, __half* d3, const float* s3,
    __half* d4, const float* s4)
{
    // sizes in 8-float units: 2097152, 2097152, 524288, 524288, 2097152
    long long i = (long long)blockIdx.x * blockDim.x + threadIdx.x;
    const float* src; __half* dst; long long off;
    if (i < 2097152)      { src = s0; dst = d0; off = i; }
    else if (i < 4194304) { src = s1; dst = d1; off = i - 2097152; }
    else if (i < 4718592) { src = s2; dst = d2; off = i - 4194304; }
    else if (i < 5242880) { src = s3; dst = d3; off = i - 4718592; }
    else                  { src = s4; dst = d4; off = i - 5242880; }
    float4 v0 = ((const float4*)src)[2 * off];
    float4 v1 = ((const float4*)src)[2 * off + 1];
    __half2 h0 = __floats2half2_rn(v0.x, v0.y);
    __half2 h1 = __floats2half2_rn(v0.z, v0.w);
    __half2 h2 = __floats2half2_rn(v1.x, v1.y);
    __half2 h3 = __floats2half2_rn(v1.z, v1.w);
    uint4 o = make_uint4(h2u(h0), h2u(h1), h2u(h2), h2u(h3));
    ((uint4*)dst)[off] = o;
}

// ---------------- FP16 GEMM: C[M,N] = A[M,K] * B[N,K]^T  --------------------
// CTA 128x128, 8 warps (4m x 2n) of 32x64, BK=32, 4-stage cp.async pipeline.
// 16 warps/SM resident (2 CTAs) for latency hiding.
// MODE: 0 = half out, 1 = half out TRANSPOSED (C^T[N][ldc]), 2 = float out.
#define GST 16384
#define GSMEM_BYTES (4 * GST)   // 65536

template <int MODE>
__global__ __launch_bounds__(256, 2) void gemm_f16(
    void* Cp, const __half* __restrict__ A, const __half* __restrict__ B,
    int K, int ldc)
{
    extern __shared__ char smem[];
    const int bm = blockIdx.y * 128, bn = blockIdx.x * 128;
    const int tid = threadIdx.x;
    const int warp = tid >> 5, lane = tid & 31;
    const int wm = (warp & 3) << 5;   // 0,32,64,96
    const int wn = (warp >> 2) << 6;  // 0,64
    const int g = lane >> 2, t = lane & 3;

    float acc[2][8][4];
#pragma unroll
    for (int a = 0; a < 2; ++a)
#pragma unroll
        for (int b = 0; b < 8; ++b)
#pragma unroll
            for (int c = 0; c < 4; ++c) acc[a][b][c] = 0.f;

    auto load_stage = [&](int s, int k0) {
        char* SA = smem + s * GST;
        char* SB = SA + 8192;
#pragma unroll
        for (int i = 0; i < 2; ++i) {
            int c = tid + (i << 8);   // 0..511
            int row = c >> 2, sub = c & 3;
            cp_async16(SA + row * 64 + sub * 16, A + (size_t)(bm + row) * K + k0 + sub * 8);
        }
#pragma unroll
        for (int i = 0; i < 2; ++i) {
            int c = tid + (i << 8);
            int row = c >> 2, sub = c & 3;
            cp_async16(SB + row * 64 + sub * 16, B + (size_t)(bn + row) * K + k0 + sub * 8);
        }
    };

    const int nIter = K >> 5;
    load_stage(0, 0);  cp_commit();
    load_stage(1, 32); cp_commit();
    load_stage(2, 64); cp_commit();

    for (int it = 0; it < nIter; ++it) {
        cp_wait<2>();
        __syncthreads();
        if (it + 3 < nIter) { load_stage((it + 3) & 3, (it + 3) << 5); cp_commit(); }

        const char* SA = smem + (it & 3) * GST;
        const char* SB = SA + 8192;

        uint4 af[2][2];
#pragma unroll
        for (int mt = 0; mt < 2; ++mt) {
            af[mt][0] = *(const uint4*)(SA + (wm + (mt << 4) + g) * 64 + (t << 4));
            af[mt][1] = *(const uint4*)(SA + (wm + (mt << 4) + 8 + g) * 64 + (t << 4));
        }
#pragma unroll
        for (int nt = 0; nt < 8; ++nt) {
            uint4 bf = *(const uint4*)(SB + (wn + (nt << 3) + g) * 64 + (t << 4));
#pragma unroll
            for (int mt = 0; mt < 2; ++mt) {
                mma_f16(acc[mt][nt], af[mt][0].x, af[mt][1].x, af[mt][0].y, af[mt][1].y, bf.x, bf.y);
                mma_f16(acc[mt][nt], af[mt][0].z, af[mt][1].z, af[mt][0].w, af[mt][1].w, bf.z, bf.w);
            }
        }
    }

#pragma unroll
    for (int mt = 0; mt < 2; ++mt) {
        int r0 = bm + wm + (mt << 4) + g;
#pragma unroll
        for (int nt = 0; nt < 8; ++nt) {
            int c0 = bn + wn + (nt << 3) + 2 * t;
            if (MODE == 2) {
                float* C = (float*)Cp;
                *(float2*)&C[(size_t)r0 * ldc + c0] = make_float2(acc[mt][nt][0], acc[mt][nt][1]);
                *(float2*)&C[(size_t)(r0 + 8) * ldc + c0] = make_float2(acc[mt][nt][2], acc[mt][nt][3]);
            } else if (MODE == 0) {
                __half* C = (__half*)Cp;
                *(__half2*)&C[(size_t)r0 * ldc + c0] = __floats2half2_rn(acc[mt][nt][0], acc[mt][nt][1]);
                *(__half2*)&C[(size_t)(r0 + 8) * ldc + c0] = __floats2half2_rn(acc[mt][nt][2], acc[mt][nt][3]);
            } else {
                __half* C = (__half*)Cp;
                C[(size_t)c0 * ldc + r0]           = __float2half_rn(acc[mt][nt][0]);
                C[(size_t)(c0 + 1) * ldc + r0]     = __float2half_rn(acc[mt][nt][1]);
                C[(size_t)c0 * ldc + r0 + 8]       = __float2half_rn(acc[mt][nt][2]);
                C[(size_t)(c0 + 1) * ldc + r0 + 8] = __float2half_rn(acc[mt][nt][3]);
            }
        }
    }
}

// ---------------- RoPE on half, in-place, with output scale -----------------
__global__ void rope_kernel(__half* __restrict__ x, const float* __restrict__ cs,
                            const float* __restrict__ sn, int nheads, float scale)
{
    int idx = blockIdx.x * blockDim.x + threadIdx.x;
    int total = 4096 * nheads * 64;
    if (idx >= total) return;
    int i = idx & 63;
    int h = (idx >> 6) % nheads;
    int tok = idx / (64 * nheads);
    int s = tok & 2047;
    float c = cs[s * 64 + i];
    float si = sn[s * 64 + i];
    __half2* p = (__half2*)(x + ((size_t)tok * nheads + h) * 128) + i;
    float2 v = __half22float2(*p);
    *p = __floats2half2_rn((v.x * c - v.y * si) * scale, (v.x * si + v.y * c) * scale);
}

// ---------------- causal GQA flash attention (fp16 mma) ---------------------
#define QT 64
#define KT 32
#define QSTR 160   // halves; 320B row stride -> conflict-free LDS.128 frags
#define VSTR 40    // halves; 80B row stride  -> conflict-free LDS.32 b-frags

__global__ __launch_bounds__(128) void attn_kernel(
    __half* __restrict__ O, const __half* __restrict__ Q,
    const __half* __restrict__ Kg, const __half* __restrict__ Vtg)
{
    __shared__ __align__(16) __half Qs[64 * QSTR];   // 20480 B
    __shared__ __align__(16) __half Ks[32 * QSTR];   // 10240 B
    __shared__ __align__(16) __half Vs[128 * VSTR];  // 10240 B

    const int qtile = blockIdx.x;
    const int h = blockIdx.y;
    const int b = blockIdx.z;
    const int kvh = h >> 2;
    const int tid = threadIdx.x;
    const int warp = tid >> 5, lane = tid & 31;
    const int g = lane >> 2, t = lane & 3;
    const int q0 = qtile * QT;

    // stage Q (pre-scaled by rope), 64 rows x 128 halves = 1024 uint4
#pragma unroll
    for (int j = 0; j < 8; ++j) {
        int c = tid + (j << 7);           // 0..1023
        int row = c >> 4, sub = c & 15;
        *(uint4*)&Qs[row * QSTR + sub * 8] =
            *(const uint4*)&Q[(size_t)(b * 2048 + q0 + row) * 4096 + h * 128 + sub * 8];
    }
    __syncthreads();

    // per-warp Q fragments: 4 k32-chunks x (rows g, g+8)
    uint4 qf[4][2];
    {
        int r = warp * 16;
#pragma unroll
        for (int c = 0; c < 4; ++c) {
            qf[c][0] = *(const uint4*)&Qs[(r + g) * QSTR + c * 32 + t * 8];
            qf[c][1] = *(const uint4*)&Qs[(r + g + 8) * QSTR + c * 32 + t * 8];
        }
    }
    __syncthreads();

    float o[16][4];
#pragma unroll
    for (int i = 0; i < 16; ++i)
#pragma unroll
        for (int j = 0; j < 4; ++j) o[i][j] = 0.f;

    float m0 = -CUDART_INF_F, m1 = -CUDART_INF_F, l0 = 0.f, l1 = 0.f;
    const int rowg0 = q0 + warp * 16 + g;
    const int rowg1 = rowg0 + 8;

    for (int kv0 = 0; kv0 < q0 + QT; kv0 += KT) {
        // stage K [32][128] and Vt [128][32]
#pragma unroll
        for (int j = 0; j < 4; ++j) {
            int c = tid + (j << 7);          // 0..511
            int row = c >> 4, sub = c & 15;
            *(uint4*)&Ks[row * QSTR + sub * 8] =
                *(const uint4*)&Kg[(size_t)(b * 2048 + kv0 + row) * 1024 + kvh * 128 + sub * 8];
        }
#pragma unroll
        for (int j = 0; j < 4; ++j) {
            int c = tid + (j << 7);
            int row = c >> 2, sub = c & 3;
            *(uint4*)&Vs[row * VSTR + sub * 8] =
                *(const uint4*)&Vtg[(size_t)(kvh * 128 + row) * 4096 + b * 2048 + kv0 + sub * 8];
        }
        __syncthreads();

        // S = Q * K^T  (m16 x n32, k=128)
        float sv[4][4];
#pragma unroll
        for (int nt = 0; nt < 4; ++nt)
#pragma unroll
            for (int j = 0; j < 4; ++j) sv[nt][j] = 0.f;

#pragma unroll
        for (int c = 0; c < 4; ++c) {
#pragma unroll
            for (int nt = 0; nt < 4; ++nt) {
                uint4 kf = *(const uint4*)&Ks[(nt * 8 + g) * QSTR + c * 32 + t * 8];
                mma_f16(sv[nt], qf[c][0].x, qf[c][1].x, qf[c][0].y, qf[c][1].y, kf.x, kf.y);
                mma_f16(sv[nt], qf[c][0].z, qf[c][1].z, qf[c][0].w, qf[c][1].w, kf.z, kf.w);
            }
        }

        // causal mask
        if (kv0 + KT > q0) {
#pragma unroll
            for (int nt = 0; nt < 4; ++nt) {
                int c0 = kv0 + nt * 8 + 2 * t;
                if (c0 > rowg0) sv[nt][0] = -CUDART_INF_F;
                if (c0 + 1 > rowg0) sv[nt][1] = -CUDART_INF_F;
                if (c0 > rowg1) sv[nt][2] = -CUDART_INF_F;
                if (c0 + 1 > rowg1) sv[nt][3] = -CUDART_INF_F;
            }
        }

        // online softmax (rows within warp)
        float mx0 = -CUDART_INF_F, mx1 = -CUDART_INF_F;
#pragma unroll
        for (int nt = 0; nt < 4; ++nt) {
            mx0 = fmaxf(mx0, fmaxf(sv[nt][0], sv[nt][1]));
            mx1 = fmaxf(mx1, fmaxf(sv[nt][2], sv[nt][3]));
        }
        mx0 = fmaxf(mx0, __shfl_xor_sync(FULLMASK, mx0, 1));
        mx0 = fmaxf(mx0, __shfl_xor_sync(FULLMASK, mx0, 2));
        mx1 = fmaxf(mx1, __shfl_xor_sync(FULLMASK, mx1, 1));
        mx1 = fmaxf(mx1, __shfl_xor_sync(FULLMASK, mx1, 2));

        float nm0 = fmaxf(m0, mx0), nm1 = fmaxf(m1, mx1);
        float a0 = exp2f(m0 - nm0), a1 = exp2f(m1 - nm1);
        m0 = nm0; m1 = nm1;

        float rs0 = 0.f, rs1 = 0.f;
#pragma unroll
        for (int nt = 0; nt < 4; ++nt) {
            sv[nt][0] = exp2f(sv[nt][0] - m0);
            sv[nt][1] = exp2f(sv[nt][1] - m0);
            sv[nt][2] = exp2f(sv[nt][2] - m1);
            sv[nt][3] = exp2f(sv[nt][3] - m1);
            rs0 += sv[nt][0] + sv[nt][1];
            rs1 += sv[nt][2] + sv[nt][3];
        }
        rs0 += __shfl_xor_sync(FULLMASK, rs0, 1);
        rs0 += __shfl_xor_sync(FULLMASK, rs0, 2);
        rs1 += __shfl_xor_sync(FULLMASK, rs1, 1);
        rs1 += __shfl_xor_sync(FULLMASK, rs1, 2);
        l0 = l0 * a0 + rs0;
        l1 = l1 * a1 + rs1;

#pragma unroll
        for (int ht = 0; ht < 16; ++ht) {
            o[ht][0] *= a0; o[ht][1] *= a0;
            o[ht][2] *= a1; o[ht][3] *= a1;
        }

        // P: C-frag layout == A-frag layout for m16n8k16 -> no shuffles
        uint32_t p00 = h2u(__floats2half2_rn(sv[0][0], sv[0][1]));
        uint32_t p01 = h2u(__floats2half2_rn(sv[0][2], sv[0][3]));
        uint32_t p02 = h2u(__floats2half2_rn(sv[1][0], sv[1][1]));
        uint32_t p03 = h2u(__floats2half2_rn(sv[1][2], sv[1][3]));
        uint32_t p10 = h2u(__floats2half2_rn(sv[2][0], sv[2][1]));
        uint32_t p11 = h2u(__floats2half2_rn(sv[2][2], sv[2][3]));
        uint32_t p12 = h2u(__floats2half2_rn(sv[3][0], sv[3][1]));
        uint32_t p13 = h2u(__floats2half2_rn(sv[3][2], sv[3][3]));

        // O += P * V  (V^T in smem: rows = hd, cols = kv)
#pragma unroll
        for (int ht = 0; ht < 16; ++ht) {
            const __half* vr = &Vs[(8 * ht + g) * VSTR];
            uint32_t b0 = *(const uint32_t*)(vr + 2 * t);
            uint32_t b1 = *(const uint32_t*)(vr + 2 * t + 8);
            mma_f16(o[ht], p00, p01, p02, p03, b0, b1);
            uint32_t b2 = *(const uint32_t*)(vr + 16 + 2 * t);
            uint32_t b3 = *(const uint32_t*)(vr + 16 + 2 * t + 8);
            mma_f16(o[ht], p10, p11, p12, p13, b2, b3);
        }
        __syncthreads();
    }

    // epilogue: normalize, store half
    float i0 = 1.f / l0, i1 = 1.f / l1;
#pragma unroll
    for (int ht = 0; ht < 16; ++ht) {
        size_t base = (size_t)(b * 2048 + rowg0) * 4096 + h * 128 + 8 * ht + 2 * t;
        *(__half2*)&O[base] = __floats2half2_rn(o[ht][0] * i0, o[ht][1] * i0);
        *(__half2*)&O[base + (size_t)8 * 4096] = __floats2half2_rn(o[ht][2] * i1, o[ht][3] * i1);
    }
}

// ---------------- entry -----------------------------------------------------
extern "C" void kernel_launch(void* const* d_in, const int* in_sizes, int n_in,
                              void* d_out, int out_size)
{
    const float* x  = (const float*)d_in[0];
    const float* wq = (const float*)d_in[1];
    const float* wk = (const float*)d_in[2];
    const float* wv = (const float*)d_in[3];
    const float* wo = (const float*)d_in[4];
    const float* fc = (const float*)d_in[5];
    const float* fs = (const float*)d_in[6];
    float* out = (float*)d_out;

    __half *xh, *wqh, *wkh, *wvh, *woh, *q, *k, *vt, *att;
    cudaGetSymbolAddress((void**)&xh,  g_xh);
    cudaGetSymbolAddress((void**)&wqh, g_wqh);
    cudaGetSymbolAddress((void**)&wkh, g_wkh);
    cudaGetSymbolAddress((void**)&wvh, g_wvh);
    cudaGetSymbolAddress((void**)&woh, g_woh);
    cudaGetSymbolAddress((void**)&q,   g_q);
    cudaGetSymbolAddress((void**)&k,   g_k);
    cudaGetSymbolAddress((void**)&vt,  g_vt);
    cudaGetSymbolAddress((void**)&att, g_att);

    cudaFuncSetAttribute(gemm_f16<0>, cudaFuncAttributeMaxDynamicSharedMemorySize, GSMEM_BYTES);
    cudaFuncSetAttribute(gemm_f16<1>, cudaFuncAttributeMaxDynamicSharedMemorySize, GSMEM_BYTES);
    cudaFuncSetAttribute(gemm_f16<2>, cudaFuncAttributeMaxDynamicSharedMemorySize, GSMEM_BYTES);

    // scale folded into Q rope: 1/sqrt(128) * log2(e)
    const float qscale = 0.08838834764831845f * 1.4426950408889634f;

    // 1: fused convert of all GEMM inputs to fp16
    conv_all_kernel<<<28672, 256>>>(xh, x, wqh, wq, wkh, wk, wvh, wv, woh, wo);

    // 2: V projection -> transposed half output g_vt [1024][4096]
    gemm_f16<1><<<dim3(8, 32), 256, GSMEM_BYTES>>>(vt, xh, wvh, 4096, 4096);

    // 3: K projection -> g_k [4096][1024]
    gemm_f16<0><<<dim3(8, 32), 256, GSMEM_BYTES>>>(k, xh, wkh, 4096, 1024);

    // 4 (profiled slot): Q projection -> g_q [4096][4096]
    gemm_f16<0><<<dim3(32, 32), 256, GSMEM_BYTES>>>(q, xh, wqh, 4096, 4096);

    // 5-6: RoPE on Q (scaled) and K
    rope_kernel<<<(4096 * 32 * 64 + 255) / 256, 256>>>(q, fc, fs, 32, qscale);
    rope_kernel<<<(4096 * 8 * 64 + 255) / 256, 256>>>(k, fc, fs, 8, 1.0f);

    // 7: attention -> g_att (half)
    attn_kernel<<<dim3(32, 32, 2), 128>>>(att, q, k, vt);

    // 8: output projection -> d_out (fp32)
    gemm_f16<2><<<dim3(32, 32), 256, GSMEM_BYTES>>>(out, att, woh, 4096, 4096);
}

// round 8
// speedup vs baseline: 2.3963x; 1.0265x over previous
#include <cuda_runtime.h>
#include <cuda_fp16.h>
#include <cstdint>
#include <math_constants.h>

#define FULLMASK 0xffffffffu

// ---------------- scratch (static device arrays; no cudaMalloc) -------------
static __device__ __half g_xh [4096u * 4096u];  // x  -> half
static __device__ __half g_wqh[4096u * 4096u];
static __device__ __half g_wkh[1024u * 4096u];
static __device__ __half g_wvh[1024u * 4096u];
static __device__ __half g_woh[4096u * 4096u];
static __device__ __half g_q  [4096u * 4096u];  // xq (roped, pre-scaled)
static __device__ __half g_k  [4096u * 1024u];  // xk (roped)
static __device__ __half g_vt [1024u * 4096u];  // xv TRANSPOSED: [hd_global][token]
static __device__ __half g_att[4096u * 4096u];  // attention out

// ---------------- helpers ---------------------------------------------------
__device__ __forceinline__ void mma_f16(float* c, uint32_t a0, uint32_t a1,
                                        uint32_t a2, uint32_t a3,
                                        uint32_t b0, uint32_t b1) {
    asm volatile(
        "mma.sync.aligned.m16n8k16.row.col.f32.f16.f16.f32 "
        "{%0,%1,%2,%3}, {%4,%5,%6,%7}, {%8,%9}, {%0,%1,%2,%3};"
        : "+f"(c[0]), "+f"(c[1]), "+f"(c[2]), "+f"(c[3])
        : "r"(a0), "r"(a1), "r"(a2), "r"(a3), "r"(b0), "r"(b1));
}

__device__ __forceinline__ void cp_async16(void* smem, const void* gmem) {
    uint32_t s = (uint32_t)__cvta_generic_to_shared(smem);
    asm volatile("cp.async.cg.shared.global [%0], [%1], 16;" :: "r"(s), "l"(gmem));
}
__device__ __forceinline__ void cp_commit() {
    asm volatile("cp.async.commit_group;" ::: "memory");
}
template <int N>
__device__ __forceinline__ void cp_wait() {
    asm volatile("cp.async.wait_group %0;" :: "n"(N) : "memory");
}
__device__ __forceinline__ uint32_t h2u(__half2 h) { return *(uint32_t*)&h; }

// ---------------- fused fp32 -> fp16 convert (5 tensors, 1 launch) ----------
__global__ void conv_all_kernel(
    __half* d0, const float* s0, __half* d1, const float* s1,
    __half* d2, const float* s2, __half* d3, const float* s3,
    __half* d4, const float* s4)
{
    // sizes in 8-float units: 2097152, 2097152, 524288, 524288, 2097152
    long long i = (long long)blockIdx.x * blockDim.x + threadIdx.x;
    const float* src; __half* dst; long long off;
    if (i < 2097152)      { src = s0; dst = d0; off = i; }
    else if (i < 4194304) { src = s1; dst = d1; off = i - 2097152; }
    else if (i < 4718592) { src = s2; dst = d2; off = i - 4194304; }
    else if (i < 5242880) { src = s3; dst = d3; off = i - 4718592; }
    else                  { src = s4; dst = d4; off = i - 5242880; }
    float4 v0 = ((const float4*)src)[2 * off];
    float4 v1 = ((const float4*)src)[2 * off + 1];
    __half2 h0 = __floats2half2_rn(v0.x, v0.y);
    __half2 h1 = __floats2half2_rn(v0.z, v0.w);
    __half2 h2 = __floats2half2_rn(v1.x, v1.y);
    __half2 h3 = __floats2half2_rn(v1.z, v1.w);
    uint4 o = make_uint4(h2u(h0), h2u(h1), h2u(h2), h2u(h3));
    ((uint4*)dst)[off] = o;
}

// ---------------- FP16 GEMM: C[M,N] = A[M,K] * B[N,K]^T  --------------------
// CTA 128x128, 8 warps (4m x 2n) of 32x64, BK=32, 5-stage cp.async pipeline,
// B-fragment software double-buffering so LDS overlaps MMA issue.
// MODE: 0 = half out, 1 = half out TRANSPOSED (C^T[N][ldc]), 2 = float out.
#define GST 16384
#define NSTG 5
#define GSMEM_BYTES (NSTG * GST)   // 81920

template <int MODE>
__global__ __launch_bounds__(256, 2) void gemm_f16(
    void* Cp, const __half* __restrict__ A, const __half* __restrict__ B,
    int K, int ldc)
{
    extern __shared__ char smem[];
    const int bm = blockIdx.y * 128, bn = blockIdx.x * 128;
    const int tid = threadIdx.x;
    const int warp = tid >> 5, lane = tid & 31;
    const int wm = (warp & 3) << 5;   // 0,32,64,96
    const int wn = (warp >> 2) << 6;  // 0,64
    const int g = lane >> 2, t = lane & 3;

    float acc[2][8][4];
#pragma unroll
    for (int a = 0; a < 2; ++a)
#pragma unroll
        for (int b = 0; b < 8; ++b)
#pragma unroll
            for (int c = 0; c < 4; ++c) acc[a][b][c] = 0.f;

    auto load_stage = [&](int s, int k0) {
        char* SA = smem + s * GST;
        char* SB = SA + 8192;
#pragma unroll
        for (int i = 0; i < 2; ++i) {
            int c = tid + (i << 8);   // 0..511
            int row = c >> 2, sub = c & 3;
            cp_async16(SA + row * 64 + sub * 16, A + (size_t)(bm + row) * K + k0 + sub * 8);
        }
#pragma unroll
        for (int i = 0; i < 2; ++i) {
            int c = tid + (i << 8);
            int row = c >> 2, sub = c & 3;
            cp_async16(SB + row * 64 + sub * 16, B + (size_t)(bn + row) * K + k0 + sub * 8);
        }
    };

    const int nIter = K >> 5;
    load_stage(0, 0);  cp_commit();
    load_stage(1, 32); cp_commit();
    load_stage(2, 64); cp_commit();
    load_stage(3, 96); cp_commit();

    int cur = 0;
    for (int it = 0; it < nIter; ++it) {
        cp_wait<3>();
        __syncthreads();

        const char* SA = smem + cur * GST;
        const char* SB = SA + 8192;

        // A fragments + first B fragment
        uint4 af[2][2];
#pragma unroll
        for (int mt = 0; mt < 2; ++mt) {
            af[mt][0] = *(const uint4*)(SA + (wm + (mt << 4) + g) * 64 + (t << 4));
            af[mt][1] = *(const uint4*)(SA + (wm + (mt << 4) + 8 + g) * 64 + (t << 4));
        }
        uint4 bf = *(const uint4*)(SB + (wn + g) * 64 + (t << 4));

        // issue next-stage loads; ALWAYS commit so group count per iter is
        // invariant (makes wait<3> deterministically complete stage `it`)
        {
            int nb = cur - 1; if (nb < 0) nb = NSTG - 1;
            if (it + 4 < nIter) load_stage(nb, (it + 4) << 5);
            cp_commit();
        }

        // MMA loop with B-fragment double buffer: LDS(nt+1) overlaps MMA(nt)
#pragma unroll
        for (int nt = 0; nt < 8; ++nt) {
            uint4 bfn;
            if (nt < 7)
                bfn = *(const uint4*)(SB + (wn + ((nt + 1) << 3) + g) * 64 + (t << 4));
#pragma unroll
            for (int mt = 0; mt < 2; ++mt) {
                mma_f16(acc[mt][nt], af[mt][0].x, af[mt][1].x, af[mt][0].y, af[mt][1].y, bf.x, bf.y);
                mma_f16(acc[mt][nt], af[mt][0].z, af[mt][1].z, af[mt][0].w, af[mt][1].w, bf.z, bf.w);
            }
            bf = bfn;
        }
        if (++cur == NSTG) cur = 0;
    }

#pragma unroll
    for (int mt = 0; mt < 2; ++mt) {
        int r0 = bm + wm + (mt << 4) + g;
#pragma unroll
        for (int nt = 0; nt < 8; ++nt) {
            int c0 = bn + wn + (nt << 3) + 2 * t;
            if (MODE == 2) {
                float* C = (float*)Cp;
                *(float2*)&C[(size_t)r0 * ldc + c0] = make_float2(acc[mt][nt][0], acc[mt][nt][1]);
                *(float2*)&C[(size_t)(r0 + 8) * ldc + c0] = make_float2(acc[mt][nt][2], acc[mt][nt][3]);
            } else if (MODE == 0) {
                __half* C = (__half*)Cp;
                *(__half2*)&C[(size_t)r0 * ldc + c0] = __floats2half2_rn(acc[mt][nt][0], acc[mt][nt][1]);
                *(__half2*)&C[(size_t)(r0 + 8) * ldc + c0] = __floats2half2_rn(acc[mt][nt][2], acc[mt][nt][3]);
            } else {
                __half* C = (__half*)Cp;
                C[(size_t)c0 * ldc + r0]           = __float2half_rn(acc[mt][nt][0]);
                C[(size_t)(c0 + 1) * ldc + r0]     = __float2half_rn(acc[mt][nt][1]);
                C[(size_t)c0 * ldc + r0 + 8]       = __float2half_rn(acc[mt][nt][2]);
                C[(size_t)(c0 + 1) * ldc + r0 + 8] = __float2half_rn(acc[mt][nt][3]);
            }
        }
    }
}

// ---------------- RoPE on half, in-place, with output scale -----------------
__global__ void rope_kernel(__half* __restrict__ x, const float* __restrict__ cs,
                            const float* __restrict__ sn, int nheads, float scale)
{
    int idx = blockIdx.x * blockDim.x + threadIdx.x;
    int total = 4096 * nheads * 64;
    if (idx >= total) return;
    int i = idx & 63;
    int h = (idx >> 6) % nheads;
    int tok = idx / (64 * nheads);
    int s = tok & 2047;
    float c = cs[s * 64 + i];
    float si = sn[s * 64 + i];
    __half2* p = (__half2*)(x + ((size_t)tok * nheads + h) * 128) + i;
    float2 v = __half22float2(*p);
    *p = __floats2half2_rn((v.x * c - v.y * si) * scale, (v.x * si + v.y * c) * scale);
}

// ---------------- causal GQA flash attention (fp16 mma) ---------------------
#define QT 64
#define KT 32
#define QSTR 160   // halves; 320B row stride -> conflict-free LDS.128 frags
#define VSTR 40    // halves; 80B row stride  -> conflict-free LDS.32 b-frags

__global__ __launch_bounds__(128) void attn_kernel(
    __half* __restrict__ O, const __half* __restrict__ Q,
    const __half* __restrict__ Kg, const __half* __restrict__ Vtg)
{
    __shared__ __align__(16) __half Qs[64 * QSTR];   // 20480 B
    __shared__ __align__(16) __half Ks[32 * QSTR];   // 10240 B
    __shared__ __align__(16) __half Vs[128 * VSTR];  // 10240 B

    const int qtile = blockIdx.x;
    const int h = blockIdx.y;
    const int b = blockIdx.z;
    const int kvh = h >> 2;
    const int tid = threadIdx.x;
    const int warp = tid >> 5, lane = tid & 31;
    const int g = lane >> 2, t = lane & 3;
    const int q0 = qtile * QT;

    // stage Q (pre-scaled by rope), 64 rows x 128 halves = 1024 uint4
#pragma unroll
    for (int j = 0; j < 8; ++j) {
        int c = tid + (j << 7);           // 0..1023
        int row = c >> 4, sub = c & 15;
        *(uint4*)&Qs[row * QSTR + sub * 8] =
            *(const uint4*)&Q[(size_t)(b * 2048 + q0 + row) * 4096 + h * 128 + sub * 8];
    }
    __syncthreads();

    // per-warp Q fragments: 4 k32-chunks x (rows g, g+8)
    uint4 qf[4][2];
    {
        int r = warp * 16;
#pragma unroll
        for (int c = 0; c < 4; ++c) {
            qf[c][0] = *(const uint4*)&Qs[(r + g) * QSTR + c * 32 + t * 8];
            qf[c][1] = *(const uint4*)&Qs[(r + g + 8) * QSTR + c * 32 + t * 8];
        }
    }
    __syncthreads();

    float o[16][4];
#pragma unroll
    for (int i = 0; i < 16; ++i)
#pragma unroll
        for (int j = 0; j < 4; ++j) o[i][j] = 0.f;

    float m0 = -CUDART_INF_F, m1 = -CUDART_INF_F, l0 = 0.f, l1 = 0.f;
    const int rowg0 = q0 + warp * 16 + g;
    const int rowg1 = rowg0 + 8;

    for (int kv0 = 0; kv0 < q0 + QT; kv0 += KT) {
        // stage K [32][128] and Vt [128][32]
#pragma unroll
        for (int j = 0; j < 4; ++j) {
            int c = tid + (j << 7);          // 0..511
            int row = c >> 4, sub = c & 15;
            *(uint4*)&Ks[row * QSTR + sub * 8] =
                *(const uint4*)&Kg[(size_t)(b * 2048 + kv0 + row) * 1024 + kvh * 128 + sub * 8];
        }
#pragma unroll
        for (int j = 0; j < 4; ++j) {
            int c = tid + (j << 7);
            int row = c >> 2, sub = c & 3;
            *(uint4*)&Vs[row * VSTR + sub * 8] =
                *(const uint4*)&Vtg[(size_t)(kvh * 128 + row) * 4096 + b * 2048 + kv0 + sub * 8];
        }
        __syncthreads();

        // S = Q * K^T  (m16 x n32, k=128)
        float sv[4][4];
#pragma unroll
        for (int nt = 0; nt < 4; ++nt)
#pragma unroll
            for (int j = 0; j < 4; ++j) sv[nt][j] = 0.f;

#pragma unroll
        for (int c = 0; c < 4; ++c) {
#pragma unroll
            for (int nt = 0; nt < 4; ++nt) {
                uint4 kf = *(const uint4*)&Ks[(nt * 8 + g) * QSTR + c * 32 + t * 8];
                mma_f16(sv[nt], qf[c][0].x, qf[c][1].x, qf[c][0].y, qf[c][1].y, kf.x, kf.y);
                mma_f16(sv[nt], qf[c][0].z, qf[c][1].z, qf[c][0].w, qf[c][1].w, kf.z, kf.w);
            }
        }

        // causal mask
        if (kv0 + KT > q0) {
#pragma unroll
            for (int nt = 0; nt < 4; ++nt) {
                int c0 = kv0 + nt * 8 + 2 * t;
                if (c0 > rowg0) sv[nt][0] = -CUDART_INF_F;
                if (c0 + 1 > rowg0) sv[nt][1] = -CUDART_INF_F;
                if (c0 > rowg1) sv[nt][2] = -CUDART_INF_F;
                if (c0 + 1 > rowg1) sv[nt][3] = -CUDART_INF_F;
            }
        }

        // online softmax (rows within warp)
        float mx0 = -CUDART_INF_F, mx1 = -CUDART_INF_F;
#pragma unroll
        for (int nt = 0; nt < 4; ++nt) {
            mx0 = fmaxf(mx0, fmaxf(sv[nt][0], sv[nt][1]));
            mx1 = fmaxf(mx1, fmaxf(sv[nt][2], sv[nt][3]));
        }
        mx0 = fmaxf(mx0, __shfl_xor_sync(FULLMASK, mx0, 1));
        mx0 = fmaxf(mx0, __shfl_xor_sync(FULLMASK, mx0, 2));
        mx1 = fmaxf(mx1, __shfl_xor_sync(FULLMASK, mx1, 1));
        mx1 = fmaxf(mx1, __shfl_xor_sync(FULLMASK, mx1, 2));

        float nm0 = fmaxf(m0, mx0), nm1 = fmaxf(m1, mx1);
        float a0 = exp2f(m0 - nm0), a1 = exp2f(m1 - nm1);
        m0 = nm0; m1 = nm1;

        float rs0 = 0.f, rs1 = 0.f;
#pragma unroll
        for (int nt = 0; nt < 4; ++nt) {
            sv[nt][0] = exp2f(sv[nt][0] - m0);
            sv[nt][1] = exp2f(sv[nt][1] - m0);
            sv[nt][2] = exp2f(sv[nt][2] - m1);
            sv[nt][3] = exp2f(sv[nt][3] - m1);
            rs0 += sv[nt][0] + sv[nt][1];
            rs1 += sv[nt][2] + sv[nt][3];
        }
        rs0 += __shfl_xor_sync(FULLMASK, rs0, 1);
        rs0 += __shfl_xor_sync(FULLMASK, rs0, 2);
        rs1 += __shfl_xor_sync(FULLMASK, rs1, 1);
        rs1 += __shfl_xor_sync(FULLMASK, rs1, 2);
        l0 = l0 * a0 + rs0;
        l1 = l1 * a1 + rs1;

#pragma unroll
        for (int ht = 0; ht < 16; ++ht) {
            o[ht][0] *= a0; o[ht][1] *= a0;
            o[ht][2] *= a1; o[ht][3] *= a1;
        }

        // P: C-frag layout == A-frag layout for m16n8k16 -> no shuffles
        uint32_t p00 = h2u(__floats2half2_rn(sv[0][0], sv[0][1]));
        uint32_t p01 = h2u(__floats2half2_rn(sv[0][2], sv[0][3]));
        uint32_t p02 = h2u(__floats2half2_rn(sv[1][0], sv[1][1]));
        uint32_t p03 = h2u(__floats2half2_rn(sv[1][2], sv[1][3]));
        uint32_t p10 = h2u(__floats2half2_rn(sv[2][0], sv[2][1]));
        uint32_t p11 = h2u(__floats2half2_rn(sv[2][2], sv[2][3]));
        uint32_t p12 = h2u(__floats2half2_rn(sv[3][0], sv[3][1]));
        uint32_t p13 = h2u(__floats2half2_rn(sv[3][2], sv[3][3]));

        // O += P * V  (V^T in smem: rows = hd, cols = kv)
#pragma unroll
        for (int ht = 0; ht < 16; ++ht) {
            const __half* vr = &Vs[(8 * ht + g) * VSTR];
            uint32_t b0 = *(const uint32_t*)(vr + 2 * t);
            uint32_t b1 = *(const uint32_t*)(vr + 2 * t + 8);
            mma_f16(o[ht], p00, p01, p02, p03, b0, b1);
            uint32_t b2 = *(const uint32_t*)(vr + 16 + 2 * t);
            uint32_t b3 = *(const uint32_t*)(vr + 16 + 2 * t + 8);
            mma_f16(o[ht], p10, p11, p12, p13, b2, b3);
        }
        __syncthreads();
    }

    // epilogue: normalize, store half
    float i0 = 1.f / l0, i1 = 1.f / l1;
#pragma unroll
    for (int ht = 0; ht < 16; ++ht) {
        size_t base = (size_t)(b * 2048 + rowg0) * 4096 + h * 128 + 8 * ht + 2 * t;
        *(__half2*)&O[base] = __floats2half2_rn(o[ht][0] * i0, o[ht][1] * i0);
        *(__half2*)&O[base + (size_t)8 * 4096] = __floats2half2_rn(o[ht][2] * i1, o[ht][3] * i1);
    }
}

// ---------------- entry -----------------------------------------------------
extern "C" void kernel_launch(void* const* d_in, const int* in_sizes, int n_in,
                              void* d_out, int out_size)
{
    const float* x  = (const float*)d_in[0];
    const float* wq = (const float*)d_in[1];
    const float* wk = (const float*)d_in[2];
    const float* wv = (const float*)d_in[3];
    const float* wo = (const float*)d_in[4];
    const float* fc = (const float*)d_in[5];
    const float* fs = (const float*)d_in[6];
    float* out = (float*)d_out;

    __half *xh, *wqh, *wkh, *wvh, *woh, *q, *k, *vt, *att;
    cudaGetSymbolAddress((void**)&xh,  g_xh);
    cudaGetSymbolAddress((void**)&wqh, g_wqh);
    cudaGetSymbolAddress((void**)&wkh, g_wkh);
    cudaGetSymbolAddress((void**)&wvh, g_wvh);
    cudaGetSymbolAddress((void**)&woh, g_woh);
    cudaGetSymbolAddress((void**)&q,   g_q);
    cudaGetSymbolAddress((void**)&k,   g_k);
    cudaGetSymbolAddress((void**)&vt,  g_vt);
    cudaGetSymbolAddress((void**)&att, g_att);

    cudaFuncSetAttribute(gemm_f16<0>, cudaFuncAttributeMaxDynamicSharedMemorySize, GSMEM_BYTES);
    cudaFuncSetAttribute(gemm_f16<1>, cudaFuncAttributeMaxDynamicSharedMemorySize, GSMEM_BYTES);
    cudaFuncSetAttribute(gemm_f16<2>, cudaFuncAttributeMaxDynamicSharedMemorySize, GSMEM_BYTES);

    // scale folded into Q rope: 1/sqrt(128) * log2(e)
    const float qscale = 0.08838834764831845f * 1.4426950408889634f;

    // 1: fused convert of all GEMM inputs to fp16
    conv_all_kernel<<<28672, 256>>>(xh, x, wqh, wq, wkh, wk, wvh, wv, woh, wo);

    // 2: V projection -> transposed half output g_vt [1024][4096]
    gemm_f16<1><<<dim3(8, 32), 256, GSMEM_BYTES>>>(vt, xh, wvh, 4096, 4096);

    // 3: K projection -> g_k [4096][1024]
    gemm_f16<0><<<dim3(8, 32), 256, GSMEM_BYTES>>>(k, xh, wkh, 4096, 1024);

    // 4 (profiled slot): Q projection -> g_q [4096][4096]
    gemm_f16<0><<<dim3(32, 32), 256, GSMEM_BYTES>>>(q, xh, wqh, 4096, 4096);

    // 5-6: RoPE on Q (scaled) and K
    rope_kernel<<<(4096 * 32 * 64 + 255) / 256, 256>>>(q, fc, fs, 32, qscale);
    rope_kernel<<<(4096 * 8 * 64 + 255) / 256, 256>>>(k, fc, fs, 8, 1.0f);

    // 7: attention -> g_att (half)
    attn_kernel<<<dim3(32, 32, 2), 128>>>(att, q, k, vt);

    // 8: output projection -> d_out (fp32)
    gemm_f16<2><<<dim3(32, 32), 256, GSMEM_BYTES>>>(out, att, woh, 4096, 4096);
}